// round 10
// baseline (speedup 1.0000x reference)
#include <cuda_runtime.h>
#include <cuda_bf16.h>
#include <math.h>
#include <cstdint>

// Problem constants
#define NF   128
#define PP   576
#define DD   1536
#define LMq  4096
#define NQk  64
#define NM1  127
#define NC   8
#define SPLIT 8
#define PPC  (PP/SPLIT)

// Float scratch
#define OFF_MP    0
#define OFF_FEAT  (SPLIT*NF*DD)
#define OFF_H     (OFF_FEAT + NM1*DD)
#define OFF_Y     (OFF_H    + NM1*DD)
#define SCRATCH_TOTAL (OFF_Y + 256)

__device__ float g_scratch[SCRATCH_TOTAL];
__device__ int   g_sel[NC + 1];

__device__ __align__(16) __nv_bfloat16 g_hiA[128 * DD];
__device__ __align__(16) __nv_bfloat16 g_loA[128 * DD];

__device__ __forceinline__ void split_bf16(float a, __nv_bfloat16& h, __nv_bfloat16& l) {
    h = __float2bfloat16(a);
    l = __float2bfloat16(a - __bfloat162float(h));
}
__device__ __forceinline__ void cpa16(uint32_t dst, const void* src) {
    asm volatile("cp.async.cg.shared.global [%0], [%1], 16;" :: "r"(dst), "l"(src));
}
__device__ __forceinline__ void ldsm_x4(uint32_t* r, uint32_t addr) {
    asm volatile("ldmatrix.sync.aligned.m8n8.x4.shared.b16 {%0,%1,%2,%3}, [%4];"
        : "=r"(r[0]), "=r"(r[1]), "=r"(r[2]), "=r"(r[3]) : "r"(addr));
}
__device__ __forceinline__ void ldsm_x4t(uint32_t* r, uint32_t addr) {
    asm volatile("ldmatrix.sync.aligned.m8n8.x4.trans.shared.b16 {%0,%1,%2,%3}, [%4];"
        : "=r"(r[0]), "=r"(r[1]), "=r"(r[2]), "=r"(r[3]) : "r"(addr));
}

// ---------------------------------------------------------------------------
// Patch partial sums (SPLIT=8: 3072 blocks, 72 patches each)
// ---------------------------------------------------------------------------
__global__ void k_mp(const float* __restrict__ v, float* __restrict__ mp2) {
    int b = blockIdx.x;
    int hh = b & (SPLIT - 1);
    int nc = b >> 3;
    int n = nc / 3, c = nc % 3;
    int d = c * 512 + threadIdx.x * 4;
    const float* base = v + (size_t)n * PP * DD + (size_t)hh * PPC * DD + d;
    float ax = 0.f, ay = 0.f, az = 0.f, aw = 0.f;
#pragma unroll 8
    for (int p = 0; p < PPC; p++) {
        float4 x = *reinterpret_cast<const float4*>(base + (size_t)p * DD);
        ax += x.x; ay += x.y; az += x.z; aw += x.w;
    }
    float4 r = make_float4(ax, ay, az, aw);
    *reinterpret_cast<float4*>(&mp2[(size_t)hh * NF * DD + (size_t)n * DD + d]) = r;
}

// ---------------------------------------------------------------------------
// Chunked-parallel momentum EMA -> hi/lo bf16 A operand
// ---------------------------------------------------------------------------
__device__ __forceinline__ float mp_mean(const float* mp2, int i, int d) {
    const float inv = 1.0f / (float)PP;
    float s = mp2[(size_t)i * DD + d];
#pragma unroll
    for (int h = 1; h < SPLIT; h++) s += mp2[(size_t)(h * NF + i) * DD + d];
    return s * inv;
}
__global__ void k_ema(const float* __restrict__ mp2,
                      __nv_bfloat16* __restrict__ hiA, __nv_bfloat16* __restrict__ loA) {
    int bx = blockIdx.x;
    int d = (bx >> 3) * 256 + threadIdx.x;
    int c = bx & 7;
    int s = c * 16;
    int w = s - 26; if (w < 0) w = 0;
    int e_end = min(s + 16, NM1);
    float prev = mp_mean(mp2, w, d);
    float e = 0.f;
    for (int i = w; i < e_end; i++) {
        float cur = mp_mean(mp2, i + 1, d);
        float diff = cur - prev;
        e = (i == w) ? diff : (0.5f * diff + 0.5f * e);
        if (i >= s) {
            __nv_bfloat16 h, l;
            split_bf16(e, h, l);
            hiA[(size_t)i * DD + d] = h;
            loA[(size_t)i * DD + d] = l;
        }
        prev = cur;
    }
    if (c == 7) {
        hiA[(size_t)NM1 * DD + d] = __float2bfloat16(0.f);
        loA[(size_t)NM1 * DD + d] = __float2bfloat16(0.f);
    }
}

// ---------------------------------------------------------------------------
// Zero fill / bias init
// ---------------------------------------------------------------------------
__global__ void k_zero(float* __restrict__ C, int total) {
    int idx = blockIdx.x * 256 + threadIdx.x;
    if (idx < total) C[idx] = 0.f;
}
__global__ void k_init_bias(float* __restrict__ C, const float* __restrict__ bias,
                            int total, int Nn) {
    int idx = blockIdx.x * 256 + threadIdx.x;
    if (idx < total) C[idx] = bias[idx % Nn];
}

// ---------------------------------------------------------------------------
// Pipelined bf16 mma.sync GEMM, fused fp32->hi/lo B conversion, 3-term split.
// Template <WM,WN>: 8 warps as WM x WN; CTA tile (WM*32) x (WN*32), BK=32.
// A smem [m][k] stride 40 (ldmatrix), B smem [k][n] stride WN*32+8 (.trans).
// 2-stage cp.async pipeline for A; reg-prefetch + convert for B. Split-K.
// ---------------------------------------------------------------------------
#define BK   32
#define ASTR 40

template <int WM, int WN>
__global__ __launch_bounds__(256, 2)
void k_gemm_fused(const __nv_bfloat16* __restrict__ hiA, const __nv_bfloat16* __restrict__ loA,
                  const float* __restrict__ B,
                  float* __restrict__ C, int M, int Ntot, int Kcta) {
    constexpr int A_ROWS = WM * 32;
    constexpr int N_TILE = WN * 32;
    constexpr int NSTR = N_TILE + 8;
    constexpr int A_ST = A_ROWS * ASTR;
    constexpr int B_ST = BK * NSTR;
    constexpr int NQ4 = N_TILE / 4;          // float4s per B row

    extern __shared__ __align__(16) unsigned char dyn[];
    __nv_bfloat16* Ahs[2];
    __nv_bfloat16* Als[2];
    __nv_bfloat16* Bhs[2];
    __nv_bfloat16* Bls[2];
    {
        __nv_bfloat16* p = reinterpret_cast<__nv_bfloat16*>(dyn);
        Ahs[0] = p;               Als[0] = Ahs[0] + A_ST;
        Ahs[1] = Als[0] + A_ST;   Als[1] = Ahs[1] + A_ST;
        Bhs[0] = Als[1] + A_ST;   Bls[0] = Bhs[0] + B_ST;
        Bhs[1] = Bls[0] + B_ST;   Bls[1] = Bhs[1] + B_ST;
    }

    const int tid = threadIdx.x;
    const int lane = tid & 31, wid = tid >> 5;
    const int wm = wid % WM, wn = wid / WM;
    const int gid = lane >> 2, qd = lane & 3;
    const int n0 = blockIdx.x * N_TILE;
    const int kb = blockIdx.z * Kcta;
    const int fr = lane & 15, fc = (lane >> 4) << 3;

    float acc[2][4][4];
#pragma unroll
    for (int i = 0; i < 2; i++)
#pragma unroll
        for (int j = 0; j < 4; j++)
#pragma unroll
            for (int q = 0; q < 4; q++) acc[i][j][q] = 0.f;

    const int a_r = tid >> 2, a_q = tid & 3;
    float4 breg[WN];

    auto loadA = [&](int kc, int s) {
#pragma unroll
        for (int it = 0; it < (A_ROWS / 64); it++) {
            int r = a_r + it * 64;
            cpa16((uint32_t)__cvta_generic_to_shared(Ahs[s] + r * ASTR + a_q * 8),
                  hiA + (size_t)r * DD + kc + a_q * 8);
            cpa16((uint32_t)__cvta_generic_to_shared(Als[s] + r * ASTR + a_q * 8),
                  loA + (size_t)r * DD + kc + a_q * 8);
        }
        asm volatile("cp.async.commit_group;" ::: "memory");
    };
    auto loadBreg = [&](int kc) {
#pragma unroll
        for (int it = 0; it < WN; it++) {
            int g = tid + it * 256;
            int k = g / NQ4, nq = g % NQ4;
            breg[it] = *reinterpret_cast<const float4*>(B + (size_t)(kc + k) * Ntot + n0 + nq * 4);
        }
    };
    auto storeB = [&](int s) {
#pragma unroll
        for (int it = 0; it < WN; it++) {
            int g = tid + it * 256;
            int k = g / NQ4, nq = g % NQ4;
            float vals[4] = {breg[it].x, breg[it].y, breg[it].z, breg[it].w};
            __nv_bfloat16 h[4], l[4];
#pragma unroll
            for (int j = 0; j < 4; j++) split_bf16(vals[j], h[j], l[j]);
            __nv_bfloat162 h01 = __halves2bfloat162(h[0], h[1]);
            __nv_bfloat162 h23 = __halves2bfloat162(h[2], h[3]);
            __nv_bfloat162 l01 = __halves2bfloat162(l[0], l[1]);
            __nv_bfloat162 l23 = __halves2bfloat162(l[2], l[3]);
            uint2 uh, ul;
            uh.x = *reinterpret_cast<uint32_t*>(&h01); uh.y = *reinterpret_cast<uint32_t*>(&h23);
            ul.x = *reinterpret_cast<uint32_t*>(&l01); ul.y = *reinterpret_cast<uint32_t*>(&l23);
            *reinterpret_cast<uint2*>(&Bhs[s][k * NSTR + nq * 4]) = uh;
            *reinterpret_cast<uint2*>(&Bls[s][k * NSTR + nq * 4]) = ul;
        }
    };
    auto compute = [&](int s) {
        const __nv_bfloat16* Ah = Ahs[s];
        const __nv_bfloat16* Al = Als[s];
        const __nv_bfloat16* Bh = Bhs[s];
        const __nv_bfloat16* Bl = Bls[s];
#pragma unroll
        for (int ks = 0; ks < 2; ks++) {
            uint32_t ah[2][4], al[2][4], bh[4][2], bl[4][2];
#pragma unroll
            for (int mt = 0; mt < 2; mt++) {
                const __nv_bfloat16* pa = Ah + (wm * 32 + mt * 16 + fr) * ASTR + ks * 16 + fc;
                ldsm_x4(ah[mt], (uint32_t)__cvta_generic_to_shared(pa));
                const __nv_bfloat16* pl = Al + (wm * 32 + mt * 16 + fr) * ASTR + ks * 16 + fc;
                ldsm_x4(al[mt], (uint32_t)__cvta_generic_to_shared(pl));
            }
#pragma unroll
            for (int ntp = 0; ntp < 2; ntp++) {
                uint32_t r[4];
                const __nv_bfloat16* pb = Bh + (ks * 16 + fr) * NSTR + wn * 32 + ntp * 16 + fc;
                ldsm_x4t(r, (uint32_t)__cvta_generic_to_shared(pb));
                bh[2 * ntp][0] = r[0]; bh[2 * ntp][1] = r[1];
                bh[2 * ntp + 1][0] = r[2]; bh[2 * ntp + 1][1] = r[3];
                const __nv_bfloat16* pbl = Bl + (ks * 16 + fr) * NSTR + wn * 32 + ntp * 16 + fc;
                ldsm_x4t(r, (uint32_t)__cvta_generic_to_shared(pbl));
                bl[2 * ntp][0] = r[0]; bl[2 * ntp][1] = r[1];
                bl[2 * ntp + 1][0] = r[2]; bl[2 * ntp + 1][1] = r[3];
            }
#pragma unroll
            for (int mt = 0; mt < 2; mt++)
#pragma unroll
                for (int nt = 0; nt < 4; nt++) {
                    asm volatile(
                        "mma.sync.aligned.m16n8k16.row.col.f32.bf16.bf16.f32 "
                        "{%0,%1,%2,%3}, {%4,%5,%6,%7}, {%8,%9}, {%0,%1,%2,%3};"
                        : "+f"(acc[mt][nt][0]), "+f"(acc[mt][nt][1]),
                          "+f"(acc[mt][nt][2]), "+f"(acc[mt][nt][3])
                        : "r"(ah[mt][0]), "r"(ah[mt][1]), "r"(ah[mt][2]), "r"(ah[mt][3]),
                          "r"(bh[nt][0]), "r"(bh[nt][1]));
                    asm volatile(
                        "mma.sync.aligned.m16n8k16.row.col.f32.bf16.bf16.f32 "
                        "{%0,%1,%2,%3}, {%4,%5,%6,%7}, {%8,%9}, {%0,%1,%2,%3};"
                        : "+f"(acc[mt][nt][0]), "+f"(acc[mt][nt][1]),
                          "+f"(acc[mt][nt][2]), "+f"(acc[mt][nt][3])
                        : "r"(al[mt][0]), "r"(al[mt][1]), "r"(al[mt][2]), "r"(al[mt][3]),
                          "r"(bh[nt][0]), "r"(bh[nt][1]));
                    asm volatile(
                        "mma.sync.aligned.m16n8k16.row.col.f32.bf16.bf16.f32 "
                        "{%0,%1,%2,%3}, {%4,%5,%6,%7}, {%8,%9}, {%0,%1,%2,%3};"
                        : "+f"(acc[mt][nt][0]), "+f"(acc[mt][nt][1]),
                          "+f"(acc[mt][nt][2]), "+f"(acc[mt][nt][3])
                        : "r"(ah[mt][0]), "r"(ah[mt][1]), "r"(ah[mt][2]), "r"(ah[mt][3]),
                          "r"(bl[nt][0]), "r"(bl[nt][1]));
                }
        }
    };

    loadA(kb, 0);
    loadBreg(kb);
    storeB(0);
    asm volatile("cp.async.wait_group 0;" ::: "memory");
    __syncthreads();

    int cur = 0;
    for (int kc = kb; kc < kb + Kcta; kc += BK) {
        bool has = (kc + BK) < (kb + Kcta);
        if (has) {
            loadA(kc + BK, cur ^ 1);
            loadBreg(kc + BK);
        }
        compute(cur);
        if (has) {
            storeB(cur ^ 1);
            asm volatile("cp.async.wait_group 0;" ::: "memory");
            __syncthreads();
        }
        cur ^= 1;
    }

#pragma unroll
    for (int mt = 0; mt < 2; mt++) {
        int r0 = wm * 32 + mt * 16 + gid;
#pragma unroll
        for (int nt = 0; nt < 4; nt++) {
            int cc = n0 + wn * 32 + nt * 8 + qd * 2;
            if (r0 < M) {
                atomicAdd(&C[(size_t)r0 * Ntot + cc],     acc[mt][nt][0]);
                atomicAdd(&C[(size_t)r0 * Ntot + cc + 1], acc[mt][nt][1]);
            }
            if (r0 + 8 < M) {
                atomicAdd(&C[(size_t)(r0 + 8) * Ntot + cc],     acc[mt][nt][2]);
                atomicAdd(&C[(size_t)(r0 + 8) * Ntot + cc + 1], acc[mt][nt][3]);
            }
        }
    }
}

#define GEMM_SMEM_12 ((4 * (128 * ASTR) + 4 * (BK * 72)) * 2)
#define GEMM_SMEM_3  ((4 * (64 * ASTR) + 4 * (BK * 136)) * 2)

// ---------------------------------------------------------------------------
// LayerNorm per row (adds deferred bias badd) -> hi/lo bf16.
// ---------------------------------------------------------------------------
__global__ void k_ln(const float* __restrict__ X, const float* __restrict__ badd,
                     __nv_bfloat16* __restrict__ hiA, __nv_bfloat16* __restrict__ loA,
                     const float* __restrict__ gam, const float* __restrict__ bet) {
    int m = blockIdx.x;
    if (m == NM1) {
        for (int d = threadIdx.x; d < DD; d += 256) {
            hiA[(size_t)m * DD + d] = __float2bfloat16(0.f);
            loA[(size_t)m * DD + d] = __float2bfloat16(0.f);
        }
        return;
    }
    const float* x = X + (size_t)m * DD;
    __shared__ float red[32];
    __shared__ float s_mu, s_rstd;

    float s = 0.f;
    for (int d = threadIdx.x; d < DD; d += 256) s += x[d] + badd[d];
    for (int o = 16; o; o >>= 1) s += __shfl_down_sync(0xffffffffu, s, o);
    int w = threadIdx.x >> 5, lane = threadIdx.x & 31;
    if (lane == 0) red[w] = s;
    __syncthreads();
    if (threadIdx.x == 0) {
        float t = 0.f;
        for (int i = 0; i < 8; i++) t += red[i];
        s_mu = t / (float)DD;
    }
    __syncthreads();
    float mu = s_mu;

    float s2 = 0.f;
    for (int d = threadIdx.x; d < DD; d += 256) {
        float v = x[d] + badd[d] - mu; s2 += v * v;
    }
    for (int o = 16; o; o >>= 1) s2 += __shfl_down_sync(0xffffffffu, s2, o);
    if (lane == 0) red[w] = s2;
    __syncthreads();
    if (threadIdx.x == 0) {
        float t = 0.f;
        for (int i = 0; i < 8; i++) t += red[i];
        s_rstd = rsqrtf(t / (float)DD + 1e-5f);
    }
    __syncthreads();
    float rstd = s_rstd;

    for (int d = threadIdx.x; d < DD; d += 256) {
        float yv = (x[d] + badd[d] - mu) * rstd * gam[d] + bet[d];
        __nv_bfloat16 h, l;
        split_bf16(yv, h, l);
        hiA[(size_t)m * DD + d] = h;
        loA[(size_t)m * DD + d] = l;
    }
}

// ---------------------------------------------------------------------------
// Gate head: deferred bias b1, exact GELU, W2 matvec, Gumbel softmax y
// ---------------------------------------------------------------------------
__global__ void k_gate(const float* __restrict__ H, const float* __restrict__ b1,
                       const float* __restrict__ W2,
                       const float* __restrict__ b2, const float* __restrict__ gu,
                       float* __restrict__ out_gate, float* __restrict__ y) {
    int m = blockIdx.x;
    const float* h = H + (size_t)m * DD;
    float a0 = 0.f, a1 = 0.f;
    for (int k = threadIdx.x; k < DD; k += 128) {
        float hr = h[k] + b1[k];
        float hv = 0.5f * hr * (1.f + erff(hr * 0.70710678118654752440f));
        a0 += hv * W2[2 * k + 0];
        a1 += hv * W2[2 * k + 1];
    }
    for (int o = 16; o; o >>= 1) {
        a0 += __shfl_down_sync(0xffffffffu, a0, o);
        a1 += __shfl_down_sync(0xffffffffu, a1, o);
    }
    __shared__ float r0[4], r1[4];
    int w = threadIdx.x >> 5, lane = threadIdx.x & 31;
    if (lane == 0) { r0[w] = a0; r1[w] = a1; }
    __syncthreads();
    if (threadIdx.x == 0) {
        float l0 = r0[0] + r0[1] + r0[2] + r0[3] + b2[0];
        float l1 = r1[0] + r1[1] + r1[2] + r1[3] + b2[1];
        out_gate[2 * m + 0] = l0;
        out_gate[2 * m + 1] = l1;
        float u0 = gu[2 * m + 0], u1 = gu[2 * m + 1];
        float g0 = -logf(-logf(u0 + 1e-20f) + 1e-20f);
        float g1 = -logf(-logf(u1 + 1e-20f) + 1e-20f);
        float s0 = (l0 + 0.1f * g0) * 2.0f;
        float s1 = (l1 + 0.1f * g1) * 2.0f;
        y[m] = 1.0f / (1.0f + expf(s0 - s1));
    }
}

// ---------------------------------------------------------------------------
// Parallel top-8 of 127 + z_hard + selection list
// ---------------------------------------------------------------------------
__global__ void k_topk(const float* __restrict__ y, float* __restrict__ out_z) {
    __shared__ float sv[128];
    __shared__ int   si[128];
    int tid = threadIdx.x;
    float val = (tid < NM1) ? y[tid] : -1e30f;
    if (tid == 0) { out_z[0] = 1.f; g_sel[0] = 0; }
    if (tid < NM1) out_z[tid + 1] = 0.f;
    __syncthreads();
    for (int r = 0; r < NC; r++) {
        sv[tid] = val; si[tid] = tid;
        __syncthreads();
        for (int o = 64; o; o >>= 1) {
            if (tid < o) {
                float ov = sv[tid + o]; int oi = si[tid + o];
                if (ov > sv[tid] || (ov == sv[tid] && oi < si[tid])) {
                    sv[tid] = ov; si[tid] = oi;
                }
            }
            __syncthreads();
        }
        int wn = si[0];
        if (tid == wn) val = -1e30f;
        if (tid == 0) { g_sel[r + 1] = wn + 1; out_z[wn + 1] = 1.f; }
        __syncthreads();
    }
}

// ---------------------------------------------------------------------------
// Pooled thumbnail features -> hi/lo bf16 rows 0..63 (GEMM3 uses M=64 tile)
// ---------------------------------------------------------------------------
__global__ void k_pool(const float* __restrict__ v,
                       __nv_bfloat16* __restrict__ hiA, __nv_bfloat16* __restrict__ loA) {
    int b = blockIdx.x;
    int q = b / 3, c = b % 3;
    int d = c * 512 + threadIdx.x * 4;
    float ax = 0.f, ay = 0.f, az = 0.f, aw = 0.f;
    for (int s = 0; s <= NC; s++) {
        int f = g_sel[s];
        const float* base = v + ((size_t)f * PP + q * 9) * DD + d;
#pragma unroll
        for (int p = 0; p < 9; p++) {
            float4 x = *reinterpret_cast<const float4*>(base + (size_t)p * DD);
            ax += x.x; ay += x.y; az += x.z; aw += x.w;
        }
    }
    const float inv = 1.0f / 81.0f;
    float vals[4] = {ax * inv, ay * inv, az * inv, aw * inv};
#pragma unroll
    for (int j = 0; j < 4; j++) {
        __nv_bfloat16 h, l;
        split_bf16(vals[j], h, l);
        hiA[(size_t)q * DD + d + j] = h;
        loA[(size_t)q * DD + d + j] = l;
    }
}

// ---------------------------------------------------------------------------
// Launch
// ---------------------------------------------------------------------------
extern "C" void kernel_launch(void* const* d_in, const int* in_sizes, int n_in,
                              void* d_out, int out_size) {
    const float* v     = (const float*)d_in[0];
    const float* gu    = (const float*)d_in[1];
    const float* W_agg = (const float*)d_in[2];
    const float* b_agg = (const float*)d_in[3];
    const float* ln_g  = (const float*)d_in[4];
    const float* ln_b  = (const float*)d_in[5];
    const float* W1    = (const float*)d_in[6];
    const float* b1    = (const float*)d_in[7];
    const float* W2    = (const float*)d_in[8];
    const float* b2    = (const float*)d_in[9];
    const float* W_th  = (const float*)d_in[10];
    const float* b_th  = (const float*)d_in[11];

    float* out       = (float*)d_out;
    float* out_gate  = out;
    float* out_thumb = out + NM1 * 2;
    float* out_z     = out_thumb + NQk * LMq;

    float* scr = nullptr;
    cudaGetSymbolAddress((void**)&scr, g_scratch);
    float* mp2  = scr + OFF_MP;
    float* feat = scr + OFF_FEAT;
    float* h    = scr + OFF_H;
    float* yv   = scr + OFF_Y;

    __nv_bfloat16 *hiA, *loA;
    cudaGetSymbolAddress((void**)&hiA, g_hiA);
    cudaGetSymbolAddress((void**)&loA, g_loA);

    cudaFuncSetAttribute(k_gemm_fused<4, 2>, cudaFuncAttributeMaxDynamicSharedMemorySize, GEMM_SMEM_12);
    cudaFuncSetAttribute(k_gemm_fused<2, 4>, cudaFuncAttributeMaxDynamicSharedMemorySize, GEMM_SMEM_3);

    // Zero feat+h accumulators, patch sums, EMA
    k_zero<<<(2 * NM1 * DD + 255) / 256, 256>>>(feat, 2 * NM1 * DD);
    k_mp<<<NF * 3 * SPLIT, 128>>>(v, mp2);
    k_ema<<<(DD / 256) * 8, 256>>>(mp2, hiA, loA);

    // GEMM1: feat = ema @ W_agg   (b_agg folded into k_ln)
    {
        dim3 grid(DD / 64, 1, 12);
        k_gemm_fused<4, 2><<<grid, 256, GEMM_SMEM_12>>>(hiA, loA, W_agg, feat, NM1, DD, DD / 12);
    }

    // LayerNorm (adds b_agg, emits hi/lo A)
    k_ln<<<NM1 + 1, 256>>>(feat, b_agg, hiA, loA, ln_g, ln_b);

    // GEMM2: h = xn @ W1   (b1 folded into k_gate)
    {
        dim3 grid(DD / 64, 1, 12);
        k_gemm_fused<4, 2><<<grid, 256, GEMM_SMEM_12>>>(hiA, loA, W1, h, NM1, DD, DD / 12);
    }

    // gate + topk + pool
    k_gate<<<NM1, 128>>>(h, b1, W2, b2, gu, out_gate, yv);
    k_topk<<<1, 128>>>(yv, out_z);
    k_pool<<<NQk * 3, 128>>>(v, hiA, loA);

    // GEMM3: thumbnail = pooled @ W_th + b_th   (M=64 tile, N=128 tile)
    k_init_bias<<<(NQk * LMq + 255) / 256, 256>>>(out_thumb, b_th, NQk * LMq, LMq);
    {
        dim3 grid(LMq / 128, 1, 6);
        k_gemm_fused<2, 4><<<grid, 256, GEMM_SMEM_3>>>(hiA, loA, W_th, out_thumb, NQk, LMq, DD / 6);
    }
}

// round 11
// speedup vs baseline: 1.1116x; 1.1116x over previous
#include <cuda_runtime.h>
#include <cuda_bf16.h>
#include <math.h>
#include <cstdint>

// Problem constants
#define NF   128
#define PP   576
#define DD   1536
#define LMq  4096
#define NQk  64
#define NM1  127
#define NC   8
#define SPLIT 4
#define PPC  (PP/SPLIT)

// Float scratch
#define OFF_MP    0
#define OFF_FEAT  (SPLIT*NF*DD)
#define OFF_H     (OFF_FEAT + NM1*DD)
#define OFF_Y     (OFF_H    + NM1*DD)
#define SCRATCH_TOTAL (OFF_Y + 256)

__device__ float g_scratch[SCRATCH_TOTAL];
__device__ int   g_sel[NC + 1];

__device__ __align__(16) __nv_bfloat16 g_hiA[128 * DD];
__device__ __align__(16) __nv_bfloat16 g_loA[128 * DD];

__device__ __forceinline__ void split_bf16(float a, __nv_bfloat16& h, __nv_bfloat16& l) {
    h = __float2bfloat16(a);
    l = __float2bfloat16(a - __bfloat162float(h));
}
__device__ __forceinline__ void cpa16(uint32_t dst, const void* src) {
    asm volatile("cp.async.cg.shared.global [%0], [%1], 16;" :: "r"(dst), "l"(src));
}
__device__ __forceinline__ void ldsm_x4(uint32_t* r, uint32_t addr) {
    asm volatile("ldmatrix.sync.aligned.m8n8.x4.shared.b16 {%0,%1,%2,%3}, [%4];"
        : "=r"(r[0]), "=r"(r[1]), "=r"(r[2]), "=r"(r[3]) : "r"(addr));
}
__device__ __forceinline__ void ldsm_x4t(uint32_t* r, uint32_t addr) {
    asm volatile("ldmatrix.sync.aligned.m8n8.x4.trans.shared.b16 {%0,%1,%2,%3}, [%4];"
        : "=r"(r[0]), "=r"(r[1]), "=r"(r[2]), "=r"(r[3]) : "r"(addr));
}

// ---------------------------------------------------------------------------
// Patch partial sums (SPLIT=4: 1536 blocks, 144 patches each — R9 config)
// ---------------------------------------------------------------------------
__global__ void k_mp(const float* __restrict__ v, float* __restrict__ mp2) {
    int b = blockIdx.x;
    int hh = b & (SPLIT - 1);
    int nc = b >> 2;
    int n = nc / 3, c = nc % 3;
    int d = c * 512 + threadIdx.x * 4;
    const float* base = v + (size_t)n * PP * DD + (size_t)hh * PPC * DD + d;
    float ax = 0.f, ay = 0.f, az = 0.f, aw = 0.f;
#pragma unroll 8
    for (int p = 0; p < PPC; p++) {
        float4 x = *reinterpret_cast<const float4*>(base + (size_t)p * DD);
        ax += x.x; ay += x.y; az += x.z; aw += x.w;
    }
    float4 r = make_float4(ax, ay, az, aw);
    *reinterpret_cast<float4*>(&mp2[(size_t)hh * NF * DD + (size_t)n * DD + d]) = r;
}

// ---------------------------------------------------------------------------
// Chunked-parallel momentum EMA -> hi/lo bf16 A operand
// ---------------------------------------------------------------------------
__device__ __forceinline__ float mp_mean(const float* mp2, int i, int d) {
    const float inv = 1.0f / (float)PP;
    float s = mp2[(size_t)i * DD + d];
#pragma unroll
    for (int h = 1; h < SPLIT; h++) s += mp2[(size_t)(h * NF + i) * DD + d];
    return s * inv;
}
__global__ void k_ema(const float* __restrict__ mp2,
                      __nv_bfloat16* __restrict__ hiA, __nv_bfloat16* __restrict__ loA) {
    int bx = blockIdx.x;
    int d = (bx >> 3) * 256 + threadIdx.x;
    int c = bx & 7;
    int s = c * 16;
    int w = s - 26; if (w < 0) w = 0;
    int e_end = min(s + 16, NM1);
    float prev = mp_mean(mp2, w, d);
    float e = 0.f;
    for (int i = w; i < e_end; i++) {
        float cur = mp_mean(mp2, i + 1, d);
        float diff = cur - prev;
        e = (i == w) ? diff : (0.5f * diff + 0.5f * e);
        if (i >= s) {
            __nv_bfloat16 h, l;
            split_bf16(e, h, l);
            hiA[(size_t)i * DD + d] = h;
            loA[(size_t)i * DD + d] = l;
        }
        prev = cur;
    }
    if (c == 7) {
        hiA[(size_t)NM1 * DD + d] = __float2bfloat16(0.f);
        loA[(size_t)NM1 * DD + d] = __float2bfloat16(0.f);
    }
}

// ---------------------------------------------------------------------------
// Zero fill / bias init
// ---------------------------------------------------------------------------
__global__ void k_zero(float* __restrict__ C, int total) {
    int idx = blockIdx.x * 256 + threadIdx.x;
    if (idx < total) C[idx] = 0.f;
}
__global__ void k_init_bias(float* __restrict__ C, const float* __restrict__ bias,
                            int total, int Nn) {
    int idx = blockIdx.x * 256 + threadIdx.x;
    if (idx < total) C[idx] = bias[idx % Nn];
}

// ---------------------------------------------------------------------------
// Pipelined bf16 mma.sync GEMM, fused fp32->hi/lo B conversion, 3-term split.
// Template <WM,WN>: 8 warps as WM x WN; CTA tile (WM*32) x (WN*32), BK=32.
// ---------------------------------------------------------------------------
#define BK   32
#define ASTR 40

template <int WM, int WN>
__global__ __launch_bounds__(256, 2)
void k_gemm_fused(const __nv_bfloat16* __restrict__ hiA, const __nv_bfloat16* __restrict__ loA,
                  const float* __restrict__ B,
                  float* __restrict__ C, int M, int Ntot, int Kcta) {
    constexpr int A_ROWS = WM * 32;
    constexpr int N_TILE = WN * 32;
    constexpr int NSTR = N_TILE + 8;
    constexpr int A_ST = A_ROWS * ASTR;
    constexpr int B_ST = BK * NSTR;
    constexpr int NQ4 = N_TILE / 4;

    extern __shared__ __align__(16) unsigned char dyn[];
    __nv_bfloat16* Ahs[2];
    __nv_bfloat16* Als[2];
    __nv_bfloat16* Bhs[2];
    __nv_bfloat16* Bls[2];
    {
        __nv_bfloat16* p = reinterpret_cast<__nv_bfloat16*>(dyn);
        Ahs[0] = p;               Als[0] = Ahs[0] + A_ST;
        Ahs[1] = Als[0] + A_ST;   Als[1] = Ahs[1] + A_ST;
        Bhs[0] = Als[1] + A_ST;   Bls[0] = Bhs[0] + B_ST;
        Bhs[1] = Bls[0] + B_ST;   Bls[1] = Bhs[1] + B_ST;
    }

    const int tid = threadIdx.x;
    const int lane = tid & 31, wid = tid >> 5;
    const int wm = wid % WM, wn = wid / WM;
    const int gid = lane >> 2, qd = lane & 3;
    const int n0 = blockIdx.x * N_TILE;
    const int kb = blockIdx.z * Kcta;
    const int fr = lane & 15, fc = (lane >> 4) << 3;

    float acc[2][4][4];
#pragma unroll
    for (int i = 0; i < 2; i++)
#pragma unroll
        for (int j = 0; j < 4; j++)
#pragma unroll
            for (int q = 0; q < 4; q++) acc[i][j][q] = 0.f;

    const int a_r = tid >> 2, a_q = tid & 3;
    float4 breg[WN];

    auto loadA = [&](int kc, int s) {
#pragma unroll
        for (int it = 0; it < (A_ROWS / 64); it++) {
            int r = a_r + it * 64;
            cpa16((uint32_t)__cvta_generic_to_shared(Ahs[s] + r * ASTR + a_q * 8),
                  hiA + (size_t)r * DD + kc + a_q * 8);
            cpa16((uint32_t)__cvta_generic_to_shared(Als[s] + r * ASTR + a_q * 8),
                  loA + (size_t)r * DD + kc + a_q * 8);
        }
        asm volatile("cp.async.commit_group;" ::: "memory");
    };
    auto loadBreg = [&](int kc) {
#pragma unroll
        for (int it = 0; it < WN; it++) {
            int g = tid + it * 256;
            int k = g / NQ4, nq = g % NQ4;
            breg[it] = *reinterpret_cast<const float4*>(B + (size_t)(kc + k) * Ntot + n0 + nq * 4);
        }
    };
    auto storeB = [&](int s) {
#pragma unroll
        for (int it = 0; it < WN; it++) {
            int g = tid + it * 256;
            int k = g / NQ4, nq = g % NQ4;
            float vals[4] = {breg[it].x, breg[it].y, breg[it].z, breg[it].w};
            __nv_bfloat16 h[4], l[4];
#pragma unroll
            for (int j = 0; j < 4; j++) split_bf16(vals[j], h[j], l[j]);
            __nv_bfloat162 h01 = __halves2bfloat162(h[0], h[1]);
            __nv_bfloat162 h23 = __halves2bfloat162(h[2], h[3]);
            __nv_bfloat162 l01 = __halves2bfloat162(l[0], l[1]);
            __nv_bfloat162 l23 = __halves2bfloat162(l[2], l[3]);
            uint2 uh, ul;
            uh.x = *reinterpret_cast<uint32_t*>(&h01); uh.y = *reinterpret_cast<uint32_t*>(&h23);
            ul.x = *reinterpret_cast<uint32_t*>(&l01); ul.y = *reinterpret_cast<uint32_t*>(&l23);
            *reinterpret_cast<uint2*>(&Bhs[s][k * NSTR + nq * 4]) = uh;
            *reinterpret_cast<uint2*>(&Bls[s][k * NSTR + nq * 4]) = ul;
        }
    };
    auto compute = [&](int s) {
        const __nv_bfloat16* Ah = Ahs[s];
        const __nv_bfloat16* Al = Als[s];
        const __nv_bfloat16* Bh = Bhs[s];
        const __nv_bfloat16* Bl = Bls[s];
#pragma unroll
        for (int ks = 0; ks < 2; ks++) {
            uint32_t ah[2][4], al[2][4], bh[4][2], bl[4][2];
#pragma unroll
            for (int mt = 0; mt < 2; mt++) {
                const __nv_bfloat16* pa = Ah + (wm * 32 + mt * 16 + fr) * ASTR + ks * 16 + fc;
                ldsm_x4(ah[mt], (uint32_t)__cvta_generic_to_shared(pa));
                const __nv_bfloat16* pl = Al + (wm * 32 + mt * 16 + fr) * ASTR + ks * 16 + fc;
                ldsm_x4(al[mt], (uint32_t)__cvta_generic_to_shared(pl));
            }
#pragma unroll
            for (int ntp = 0; ntp < 2; ntp++) {
                uint32_t r[4];
                const __nv_bfloat16* pb = Bh + (ks * 16 + fr) * NSTR + wn * 32 + ntp * 16 + fc;
                ldsm_x4t(r, (uint32_t)__cvta_generic_to_shared(pb));
                bh[2 * ntp][0] = r[0]; bh[2 * ntp][1] = r[1];
                bh[2 * ntp + 1][0] = r[2]; bh[2 * ntp + 1][1] = r[3];
                const __nv_bfloat16* pbl = Bl + (ks * 16 + fr) * NSTR + wn * 32 + ntp * 16 + fc;
                ldsm_x4t(r, (uint32_t)__cvta_generic_to_shared(pbl));
                bl[2 * ntp][0] = r[0]; bl[2 * ntp][1] = r[1];
                bl[2 * ntp + 1][0] = r[2]; bl[2 * ntp + 1][1] = r[3];
            }
#pragma unroll
            for (int mt = 0; mt < 2; mt++)
#pragma unroll
                for (int nt = 0; nt < 4; nt++) {
                    asm volatile(
                        "mma.sync.aligned.m16n8k16.row.col.f32.bf16.bf16.f32 "
                        "{%0,%1,%2,%3}, {%4,%5,%6,%7}, {%8,%9}, {%0,%1,%2,%3};"
                        : "+f"(acc[mt][nt][0]), "+f"(acc[mt][nt][1]),
                          "+f"(acc[mt][nt][2]), "+f"(acc[mt][nt][3])
                        : "r"(ah[mt][0]), "r"(ah[mt][1]), "r"(ah[mt][2]), "r"(ah[mt][3]),
                          "r"(bh[nt][0]), "r"(bh[nt][1]));
                    asm volatile(
                        "mma.sync.aligned.m16n8k16.row.col.f32.bf16.bf16.f32 "
                        "{%0,%1,%2,%3}, {%4,%5,%6,%7}, {%8,%9}, {%0,%1,%2,%3};"
                        : "+f"(acc[mt][nt][0]), "+f"(acc[mt][nt][1]),
                          "+f"(acc[mt][nt][2]), "+f"(acc[mt][nt][3])
                        : "r"(al[mt][0]), "r"(al[mt][1]), "r"(al[mt][2]), "r"(al[mt][3]),
                          "r"(bh[nt][0]), "r"(bh[nt][1]));
                    asm volatile(
                        "mma.sync.aligned.m16n8k16.row.col.f32.bf16.bf16.f32 "
                        "{%0,%1,%2,%3}, {%4,%5,%6,%7}, {%8,%9}, {%0,%1,%2,%3};"
                        : "+f"(acc[mt][nt][0]), "+f"(acc[mt][nt][1]),
                          "+f"(acc[mt][nt][2]), "+f"(acc[mt][nt][3])
                        : "r"(ah[mt][0]), "r"(ah[mt][1]), "r"(ah[mt][2]), "r"(ah[mt][3]),
                          "r"(bl[nt][0]), "r"(bl[nt][1]));
                }
        }
    };

    loadA(kb, 0);
    loadBreg(kb);
    storeB(0);
    asm volatile("cp.async.wait_group 0;" ::: "memory");
    __syncthreads();

    int cur = 0;
    for (int kc = kb; kc < kb + Kcta; kc += BK) {
        bool has = (kc + BK) < (kb + Kcta);
        if (has) {
            loadA(kc + BK, cur ^ 1);
            loadBreg(kc + BK);
        }
        compute(cur);
        if (has) {
            storeB(cur ^ 1);
            asm volatile("cp.async.wait_group 0;" ::: "memory");
            __syncthreads();
        }
        cur ^= 1;
    }

#pragma unroll
    for (int mt = 0; mt < 2; mt++) {
        int r0 = wm * 32 + mt * 16 + gid;
#pragma unroll
        for (int nt = 0; nt < 4; nt++) {
            int cc = n0 + wn * 32 + nt * 8 + qd * 2;
            if (r0 < M) {
                atomicAdd(&C[(size_t)r0 * Ntot + cc],     acc[mt][nt][0]);
                atomicAdd(&C[(size_t)r0 * Ntot + cc + 1], acc[mt][nt][1]);
            }
            if (r0 + 8 < M) {
                atomicAdd(&C[(size_t)(r0 + 8) * Ntot + cc],     acc[mt][nt][2]);
                atomicAdd(&C[(size_t)(r0 + 8) * Ntot + cc + 1], acc[mt][nt][3]);
            }
        }
    }
}

#define GEMM_SMEM_12 ((4 * (128 * ASTR) + 4 * (BK * 72)) * 2)
#define GEMM_SMEM_3  ((4 * (64 * ASTR) + 4 * (BK * 136)) * 2)

// ---------------------------------------------------------------------------
// LayerNorm per row (adds deferred bias badd) -> hi/lo bf16.
// ---------------------------------------------------------------------------
__global__ void k_ln(const float* __restrict__ X, const float* __restrict__ badd,
                     __nv_bfloat16* __restrict__ hiA, __nv_bfloat16* __restrict__ loA,
                     const float* __restrict__ gam, const float* __restrict__ bet) {
    int m = blockIdx.x;
    if (m == NM1) {
        for (int d = threadIdx.x; d < DD; d += 256) {
            hiA[(size_t)m * DD + d] = __float2bfloat16(0.f);
            loA[(size_t)m * DD + d] = __float2bfloat16(0.f);
        }
        return;
    }
    const float* x = X + (size_t)m * DD;
    __shared__ float red[32];
    __shared__ float s_mu, s_rstd;

    float s = 0.f;
    for (int d = threadIdx.x; d < DD; d += 256) s += x[d] + badd[d];
    for (int o = 16; o; o >>= 1) s += __shfl_down_sync(0xffffffffu, s, o);
    int w = threadIdx.x >> 5, lane = threadIdx.x & 31;
    if (lane == 0) red[w] = s;
    __syncthreads();
    if (threadIdx.x == 0) {
        float t = 0.f;
        for (int i = 0; i < 8; i++) t += red[i];
        s_mu = t / (float)DD;
    }
    __syncthreads();
    float mu = s_mu;

    float s2 = 0.f;
    for (int d = threadIdx.x; d < DD; d += 256) {
        float v = x[d] + badd[d] - mu; s2 += v * v;
    }
    for (int o = 16; o; o >>= 1) s2 += __shfl_down_sync(0xffffffffu, s2, o);
    if (lane == 0) red[w] = s2;
    __syncthreads();
    if (threadIdx.x == 0) {
        float t = 0.f;
        for (int i = 0; i < 8; i++) t += red[i];
        s_rstd = rsqrtf(t / (float)DD + 1e-5f);
    }
    __syncthreads();
    float rstd = s_rstd;

    for (int d = threadIdx.x; d < DD; d += 256) {
        float yv = (x[d] + badd[d] - mu) * rstd * gam[d] + bet[d];
        __nv_bfloat16 h, l;
        split_bf16(yv, h, l);
        hiA[(size_t)m * DD + d] = h;
        loA[(size_t)m * DD + d] = l;
    }
}

// ---------------------------------------------------------------------------
// Gate head: deferred bias b1, exact GELU, W2 matvec, Gumbel softmax y
// ---------------------------------------------------------------------------
__global__ void k_gate(const float* __restrict__ H, const float* __restrict__ b1,
                       const float* __restrict__ W2,
                       const float* __restrict__ b2, const float* __restrict__ gu,
                       float* __restrict__ out_gate, float* __restrict__ y) {
    int m = blockIdx.x;
    const float* h = H + (size_t)m * DD;
    float a0 = 0.f, a1 = 0.f;
    for (int k = threadIdx.x; k < DD; k += 128) {
        float hr = h[k] + b1[k];
        float hv = 0.5f * hr * (1.f + erff(hr * 0.70710678118654752440f));
        a0 += hv * W2[2 * k + 0];
        a1 += hv * W2[2 * k + 1];
    }
    for (int o = 16; o; o >>= 1) {
        a0 += __shfl_down_sync(0xffffffffu, a0, o);
        a1 += __shfl_down_sync(0xffffffffu, a1, o);
    }
    __shared__ float r0[4], r1[4];
    int w = threadIdx.x >> 5, lane = threadIdx.x & 31;
    if (lane == 0) { r0[w] = a0; r1[w] = a1; }
    __syncthreads();
    if (threadIdx.x == 0) {
        float l0 = r0[0] + r0[1] + r0[2] + r0[3] + b2[0];
        float l1 = r1[0] + r1[1] + r1[2] + r1[3] + b2[1];
        out_gate[2 * m + 0] = l0;
        out_gate[2 * m + 1] = l1;
        float u0 = gu[2 * m + 0], u1 = gu[2 * m + 1];
        float g0 = -logf(-logf(u0 + 1e-20f) + 1e-20f);
        float g1 = -logf(-logf(u1 + 1e-20f) + 1e-20f);
        float s0 = (l0 + 0.1f * g0) * 2.0f;
        float s1 = (l1 + 0.1f * g1) * 2.0f;
        y[m] = 1.0f / (1.0f + expf(s0 - s1));
    }
}

// ---------------------------------------------------------------------------
// Parallel top-8 of 127 + z_hard + selection list
// ---------------------------------------------------------------------------
__global__ void k_topk(const float* __restrict__ y, float* __restrict__ out_z) {
    __shared__ float sv[128];
    __shared__ int   si[128];
    int tid = threadIdx.x;
    float val = (tid < NM1) ? y[tid] : -1e30f;
    if (tid == 0) { out_z[0] = 1.f; g_sel[0] = 0; }
    if (tid < NM1) out_z[tid + 1] = 0.f;
    __syncthreads();
    for (int r = 0; r < NC; r++) {
        sv[tid] = val; si[tid] = tid;
        __syncthreads();
        for (int o = 64; o; o >>= 1) {
            if (tid < o) {
                float ov = sv[tid + o]; int oi = si[tid + o];
                if (ov > sv[tid] || (ov == sv[tid] && oi < si[tid])) {
                    sv[tid] = ov; si[tid] = oi;
                }
            }
            __syncthreads();
        }
        int wn = si[0];
        if (tid == wn) val = -1e30f;
        if (tid == 0) { g_sel[r + 1] = wn + 1; out_z[wn + 1] = 1.f; }
        __syncthreads();
    }
}

// ---------------------------------------------------------------------------
// Pooled thumbnail features -> hi/lo bf16 rows 0..63 (GEMM3 uses M=64 tile)
// ---------------------------------------------------------------------------
__global__ void k_pool(const float* __restrict__ v,
                       __nv_bfloat16* __restrict__ hiA, __nv_bfloat16* __restrict__ loA) {
    int b = blockIdx.x;
    int q = b / 3, c = b % 3;
    int d = c * 512 + threadIdx.x * 4;
    float ax = 0.f, ay = 0.f, az = 0.f, aw = 0.f;
    for (int s = 0; s <= NC; s++) {
        int f = g_sel[s];
        const float* base = v + ((size_t)f * PP + q * 9) * DD + d;
#pragma unroll
        for (int p = 0; p < 9; p++) {
            float4 x = *reinterpret_cast<const float4*>(base + (size_t)p * DD);
            ax += x.x; ay += x.y; az += x.z; aw += x.w;
        }
    }
    const float inv = 1.0f / 81.0f;
    float vals[4] = {ax * inv, ay * inv, az * inv, aw * inv};
#pragma unroll
    for (int j = 0; j < 4; j++) {
        __nv_bfloat16 h, l;
        split_bf16(vals[j], h, l);
        hiA[(size_t)q * DD + d + j] = h;
        loA[(size_t)q * DD + d + j] = l;
    }
}

// ---------------------------------------------------------------------------
// Launch
// ---------------------------------------------------------------------------
extern "C" void kernel_launch(void* const* d_in, const int* in_sizes, int n_in,
                              void* d_out, int out_size) {
    const float* v     = (const float*)d_in[0];
    const float* gu    = (const float*)d_in[1];
    const float* W_agg = (const float*)d_in[2];
    const float* b_agg = (const float*)d_in[3];
    const float* ln_g  = (const float*)d_in[4];
    const float* ln_b  = (const float*)d_in[5];
    const float* W1    = (const float*)d_in[6];
    const float* b1    = (const float*)d_in[7];
    const float* W2    = (const float*)d_in[8];
    const float* b2    = (const float*)d_in[9];
    const float* W_th  = (const float*)d_in[10];
    const float* b_th  = (const float*)d_in[11];

    float* out       = (float*)d_out;
    float* out_gate  = out;
    float* out_thumb = out + NM1 * 2;
    float* out_z     = out_thumb + NQk * LMq;

    float* scr = nullptr;
    cudaGetSymbolAddress((void**)&scr, g_scratch);
    float* mp2  = scr + OFF_MP;
    float* feat = scr + OFF_FEAT;
    float* h    = scr + OFF_H;
    float* yv   = scr + OFF_Y;

    __nv_bfloat16 *hiA, *loA;
    cudaGetSymbolAddress((void**)&hiA, g_hiA);
    cudaGetSymbolAddress((void**)&loA, g_loA);

    cudaFuncSetAttribute(k_gemm_fused<4, 2>, cudaFuncAttributeMaxDynamicSharedMemorySize, GEMM_SMEM_12);
    cudaFuncSetAttribute(k_gemm_fused<2, 4>, cudaFuncAttributeMaxDynamicSharedMemorySize, GEMM_SMEM_3);

    // Zero feat+h accumulators, patch sums, EMA
    k_zero<<<(2 * NM1 * DD + 255) / 256, 256>>>(feat, 2 * NM1 * DD);
    k_mp<<<NF * 3 * SPLIT, 128>>>(v, mp2);
    k_ema<<<(DD / 256) * 8, 256>>>(mp2, hiA, loA);

    // GEMM1: feat = ema @ W_agg   (b_agg folded into k_ln)
    {
        dim3 grid(DD / 64, 1, 12);
        k_gemm_fused<4, 2><<<grid, 256, GEMM_SMEM_12>>>(hiA, loA, W_agg, feat, NM1, DD, DD / 12);
    }

    // LayerNorm (adds b_agg, emits hi/lo A)
    k_ln<<<NM1 + 1, 256>>>(feat, b_agg, hiA, loA, ln_g, ln_b);

    // GEMM2: h = xn @ W1   (b1 folded into k_gate)
    {
        dim3 grid(DD / 64, 1, 12);
        k_gemm_fused<4, 2><<<grid, 256, GEMM_SMEM_12>>>(hiA, loA, W1, h, NM1, DD, DD / 12);
    }

    // gate + topk + pool
    k_gate<<<NM1, 128>>>(h, b1, W2, b2, gu, out_gate, yv);
    k_topk<<<1, 128>>>(yv, out_z);
    k_pool<<<NQk * 3, 128>>>(v, hiA, loA);

    // GEMM3: thumbnail = pooled @ W_th + b_th   (M=64 tile, N=128 tile)
    k_init_bias<<<(NQk * LMq + 255) / 256, 256>>>(out_thumb, b_th, NQk * LMq, LMq);
    {
        dim3 grid(LMq / 128, 1, 6);
        k_gemm_fused<2, 4><<<grid, 256, GEMM_SMEM_3>>>(hiA, loA, W_th, out_thumb, NQk, LMq, DD / 6);
    }
}

// round 12
// speedup vs baseline: 1.1125x; 1.0008x over previous
#include <cuda_runtime.h>
#include <cuda_bf16.h>
#include <math.h>
#include <cstdint>

// Problem constants
#define NF   128
#define PP   576
#define DD   1536
#define LMq  4096
#define NQk  64
#define NM1  127
#define NC   8
#define SPLIT 4
#define PPC  (PP/SPLIT)

// Float scratch
#define OFF_MP    0
#define OFF_FEAT  (SPLIT*NF*DD)
#define OFF_H     (OFF_FEAT + NM1*DD)
#define OFF_Y     (OFF_H    + NM1*DD)
#define SCRATCH_TOTAL (OFF_Y + 256)

__device__ float g_scratch[SCRATCH_TOTAL];
__device__ int   g_sel[NC + 1];

__device__ __align__(16) __nv_bfloat16 g_hiA[128 * DD];
__device__ __align__(16) __nv_bfloat16 g_loA[128 * DD];

__device__ __forceinline__ void split_bf16(float a, __nv_bfloat16& h, __nv_bfloat16& l) {
    h = __float2bfloat16(a);
    l = __float2bfloat16(a - __bfloat162float(h));
}
__device__ __forceinline__ void cpa16(uint32_t dst, const void* src) {
    asm volatile("cp.async.cg.shared.global [%0], [%1], 16;" :: "r"(dst), "l"(src));
}
__device__ __forceinline__ void ldsm_x4(uint32_t* r, uint32_t addr) {
    asm volatile("ldmatrix.sync.aligned.m8n8.x4.shared.b16 {%0,%1,%2,%3}, [%4];"
        : "=r"(r[0]), "=r"(r[1]), "=r"(r[2]), "=r"(r[3]) : "r"(addr));
}
__device__ __forceinline__ void ldsm_x4t(uint32_t* r, uint32_t addr) {
    asm volatile("ldmatrix.sync.aligned.m8n8.x4.trans.shared.b16 {%0,%1,%2,%3}, [%4];"
        : "=r"(r[0]), "=r"(r[1]), "=r"(r[2]), "=r"(r[3]) : "r"(addr));
}

// ---------------------------------------------------------------------------
// Patch partial sums (SPLIT=4, all CTAs resident in one wave) — streaming loads
// ---------------------------------------------------------------------------
__global__ void k_mp(const float* __restrict__ v, float* __restrict__ mp2) {
    int b = blockIdx.x;
    int hh = b & (SPLIT - 1);
    int nc = b >> 2;
    int n = nc / 3, c = nc % 3;
    int d = c * 512 + threadIdx.x * 4;
    const float* base = v + (size_t)n * PP * DD + (size_t)hh * PPC * DD + d;
    float ax = 0.f, ay = 0.f, az = 0.f, aw = 0.f;
#pragma unroll 8
    for (int p = 0; p < PPC; p++) {
        float4 x = __ldcs(reinterpret_cast<const float4*>(base + (size_t)p * DD));
        ax += x.x; ay += x.y; az += x.z; aw += x.w;
    }
    float4 r = make_float4(ax, ay, az, aw);
    *reinterpret_cast<float4*>(&mp2[(size_t)hh * NF * DD + (size_t)n * DD + d]) = r;
}

// ---------------------------------------------------------------------------
// Chunked-parallel momentum EMA -> hi/lo bf16 A operand
// ---------------------------------------------------------------------------
__device__ __forceinline__ float mp_mean(const float* mp2, int i, int d) {
    const float inv = 1.0f / (float)PP;
    float s = mp2[(size_t)i * DD + d];
#pragma unroll
    for (int h = 1; h < SPLIT; h++) s += mp2[(size_t)(h * NF + i) * DD + d];
    return s * inv;
}
__global__ void k_ema(const float* __restrict__ mp2,
                      __nv_bfloat16* __restrict__ hiA, __nv_bfloat16* __restrict__ loA) {
    int bx = blockIdx.x;
    int d = (bx >> 3) * 256 + threadIdx.x;
    int c = bx & 7;
    int s = c * 16;
    int w = s - 26; if (w < 0) w = 0;
    int e_end = min(s + 16, NM1);
    float prev = mp_mean(mp2, w, d);
    float e = 0.f;
    for (int i = w; i < e_end; i++) {
        float cur = mp_mean(mp2, i + 1, d);
        float diff = cur - prev;
        e = (i == w) ? diff : (0.5f * diff + 0.5f * e);
        if (i >= s) {
            __nv_bfloat16 h, l;
            split_bf16(e, h, l);
            hiA[(size_t)i * DD + d] = h;
            loA[(size_t)i * DD + d] = l;
        }
        prev = cur;
    }
    if (c == 7) {
        hiA[(size_t)NM1 * DD + d] = __float2bfloat16(0.f);
        loA[(size_t)NM1 * DD + d] = __float2bfloat16(0.f);
    }
}

// ---------------------------------------------------------------------------
// Zero fill / bias init
// ---------------------------------------------------------------------------
__global__ void k_zero(float* __restrict__ C, int total) {
    int idx = blockIdx.x * 256 + threadIdx.x;
    if (idx < total) C[idx] = 0.f;
}
__global__ void k_init_bias(float* __restrict__ C, const float* __restrict__ bias,
                            int total, int Nn) {
    int idx = blockIdx.x * 256 + threadIdx.x;
    if (idx < total) C[idx] = bias[idx % Nn];
}

// ---------------------------------------------------------------------------
// Pipelined bf16 mma.sync GEMM, fused fp32->hi/lo B conversion, 3-term split.
// Template <WM,WN>: 8 warps as WM x WN; CTA tile (WM*32) x (WN*32), BK=32.
// 2-stage smem; A via cp.async; B global loads prefetched 2 chunks ahead
// into a 2-slot register ring so DRAM latency is hidden.
// ---------------------------------------------------------------------------
#define BK   32
#define ASTR 40

template <int WM, int WN>
__global__ __launch_bounds__(256, 2)
void k_gemm_fused(const __nv_bfloat16* __restrict__ hiA, const __nv_bfloat16* __restrict__ loA,
                  const float* __restrict__ B,
                  float* __restrict__ C, int M, int Ntot, int Kcta) {
    constexpr int A_ROWS = WM * 32;
    constexpr int N_TILE = WN * 32;
    constexpr int NSTR = N_TILE + 8;
    constexpr int A_ST = A_ROWS * ASTR;
    constexpr int B_ST = BK * NSTR;
    constexpr int NQ4 = N_TILE / 4;

    extern __shared__ __align__(16) unsigned char dyn[];
    __nv_bfloat16* Ahs[2];
    __nv_bfloat16* Als[2];
    __nv_bfloat16* Bhs[2];
    __nv_bfloat16* Bls[2];
    {
        __nv_bfloat16* p = reinterpret_cast<__nv_bfloat16*>(dyn);
        Ahs[0] = p;               Als[0] = Ahs[0] + A_ST;
        Ahs[1] = Als[0] + A_ST;   Als[1] = Ahs[1] + A_ST;
        Bhs[0] = Als[1] + A_ST;   Bls[0] = Bhs[0] + B_ST;
        Bhs[1] = Bls[0] + B_ST;   Bls[1] = Bhs[1] + B_ST;
    }

    const int tid = threadIdx.x;
    const int lane = tid & 31, wid = tid >> 5;
    const int wm = wid % WM, wn = wid / WM;
    const int gid = lane >> 2, qd = lane & 3;
    const int n0 = blockIdx.x * N_TILE;
    const int kb = blockIdx.z * Kcta;
    const int fr = lane & 15, fc = (lane >> 4) << 3;

    float acc[2][4][4];
#pragma unroll
    for (int i = 0; i < 2; i++)
#pragma unroll
        for (int j = 0; j < 4; j++)
#pragma unroll
            for (int q = 0; q < 4; q++) acc[i][j][q] = 0.f;

    const int a_r = tid >> 2, a_q = tid & 3;
    float4 breg[2][WN];                 // 2-slot register ring for B

    auto loadA = [&](int kc, int s) {
#pragma unroll
        for (int it = 0; it < (A_ROWS / 64); it++) {
            int r = a_r + it * 64;
            cpa16((uint32_t)__cvta_generic_to_shared(Ahs[s] + r * ASTR + a_q * 8),
                  hiA + (size_t)r * DD + kc + a_q * 8);
            cpa16((uint32_t)__cvta_generic_to_shared(Als[s] + r * ASTR + a_q * 8),
                  loA + (size_t)r * DD + kc + a_q * 8);
        }
        asm volatile("cp.async.commit_group;" ::: "memory");
    };
    auto loadBreg = [&](int kc, int slot) {
#pragma unroll
        for (int it = 0; it < WN; it++) {
            int g = tid + it * 256;
            int k = g / NQ4, nq = g % NQ4;
            breg[slot][it] = *reinterpret_cast<const float4*>(B + (size_t)(kc + k) * Ntot + n0 + nq * 4);
        }
    };
    auto storeB = [&](int s, int slot) {
#pragma unroll
        for (int it = 0; it < WN; it++) {
            int g = tid + it * 256;
            int k = g / NQ4, nq = g % NQ4;
            float vals[4] = {breg[slot][it].x, breg[slot][it].y, breg[slot][it].z, breg[slot][it].w};
            __nv_bfloat16 h[4], l[4];
#pragma unroll
            for (int j = 0; j < 4; j++) split_bf16(vals[j], h[j], l[j]);
            __nv_bfloat162 h01 = __halves2bfloat162(h[0], h[1]);
            __nv_bfloat162 h23 = __halves2bfloat162(h[2], h[3]);
            __nv_bfloat162 l01 = __halves2bfloat162(l[0], l[1]);
            __nv_bfloat162 l23 = __halves2bfloat162(l[2], l[3]);
            uint2 uh, ul;
            uh.x = *reinterpret_cast<uint32_t*>(&h01); uh.y = *reinterpret_cast<uint32_t*>(&h23);
            ul.x = *reinterpret_cast<uint32_t*>(&l01); ul.y = *reinterpret_cast<uint32_t*>(&l23);
            *reinterpret_cast<uint2*>(&Bhs[s][k * NSTR + nq * 4]) = uh;
            *reinterpret_cast<uint2*>(&Bls[s][k * NSTR + nq * 4]) = ul;
        }
    };
    auto compute = [&](int s) {
        const __nv_bfloat16* Ah = Ahs[s];
        const __nv_bfloat16* Al = Als[s];
        const __nv_bfloat16* Bh = Bhs[s];
        const __nv_bfloat16* Bl = Bls[s];
#pragma unroll
        for (int ks = 0; ks < 2; ks++) {
            uint32_t ah[2][4], al[2][4], bh[4][2], bl[4][2];
#pragma unroll
            for (int mt = 0; mt < 2; mt++) {
                const __nv_bfloat16* pa = Ah + (wm * 32 + mt * 16 + fr) * ASTR + ks * 16 + fc;
                ldsm_x4(ah[mt], (uint32_t)__cvta_generic_to_shared(pa));
                const __nv_bfloat16* pl = Al + (wm * 32 + mt * 16 + fr) * ASTR + ks * 16 + fc;
                ldsm_x4(al[mt], (uint32_t)__cvta_generic_to_shared(pl));
            }
#pragma unroll
            for (int ntp = 0; ntp < 2; ntp++) {
                uint32_t r[4];
                const __nv_bfloat16* pb = Bh + (ks * 16 + fr) * NSTR + wn * 32 + ntp * 16 + fc;
                ldsm_x4t(r, (uint32_t)__cvta_generic_to_shared(pb));
                bh[2 * ntp][0] = r[0]; bh[2 * ntp][1] = r[1];
                bh[2 * ntp + 1][0] = r[2]; bh[2 * ntp + 1][1] = r[3];
                const __nv_bfloat16* pbl = Bl + (ks * 16 + fr) * NSTR + wn * 32 + ntp * 16 + fc;
                ldsm_x4t(r, (uint32_t)__cvta_generic_to_shared(pbl));
                bl[2 * ntp][0] = r[0]; bl[2 * ntp][1] = r[1];
                bl[2 * ntp + 1][0] = r[2]; bl[2 * ntp + 1][1] = r[3];
            }
#pragma unroll
            for (int mt = 0; mt < 2; mt++)
#pragma unroll
                for (int nt = 0; nt < 4; nt++) {
                    asm volatile(
                        "mma.sync.aligned.m16n8k16.row.col.f32.bf16.bf16.f32 "
                        "{%0,%1,%2,%3}, {%4,%5,%6,%7}, {%8,%9}, {%0,%1,%2,%3};"
                        : "+f"(acc[mt][nt][0]), "+f"(acc[mt][nt][1]),
                          "+f"(acc[mt][nt][2]), "+f"(acc[mt][nt][3])
                        : "r"(ah[mt][0]), "r"(ah[mt][1]), "r"(ah[mt][2]), "r"(ah[mt][3]),
                          "r"(bh[nt][0]), "r"(bh[nt][1]));
                    asm volatile(
                        "mma.sync.aligned.m16n8k16.row.col.f32.bf16.bf16.f32 "
                        "{%0,%1,%2,%3}, {%4,%5,%6,%7}, {%8,%9}, {%0,%1,%2,%3};"
                        : "+f"(acc[mt][nt][0]), "+f"(acc[mt][nt][1]),
                          "+f"(acc[mt][nt][2]), "+f"(acc[mt][nt][3])
                        : "r"(al[mt][0]), "r"(al[mt][1]), "r"(al[mt][2]), "r"(al[mt][3]),
                          "r"(bh[nt][0]), "r"(bh[nt][1]));
                    asm volatile(
                        "mma.sync.aligned.m16n8k16.row.col.f32.bf16.bf16.f32 "
                        "{%0,%1,%2,%3}, {%4,%5,%6,%7}, {%8,%9}, {%0,%1,%2,%3};"
                        : "+f"(acc[mt][nt][0]), "+f"(acc[mt][nt][1]),
                          "+f"(acc[mt][nt][2]), "+f"(acc[mt][nt][3])
                        : "r"(ah[mt][0]), "r"(ah[mt][1]), "r"(ah[mt][2]), "r"(ah[mt][3]),
                          "r"(bl[nt][0]), "r"(bl[nt][1]));
                }
        }
    };

    const int nch = Kcta / BK;
    // Prologue: chunk0 A + B, store B0; kick off chunk1's B load
    loadA(kb, 0);
    loadBreg(kb, 0);
    storeB(0, 0);
    loadBreg(kb + BK, 1);
    asm volatile("cp.async.wait_group 0;" ::: "memory");
    __syncthreads();

    int cur = 0;
    for (int ci = 0; ci < nch; ci++) {
        if (ci + 1 < nch) loadA(kb + (ci + 1) * BK, cur ^ 1);
        if (ci + 2 < nch) loadBreg(kb + (ci + 2) * BK, ci & 1);  // 2 chunks ahead
        compute(cur);
        if (ci + 1 < nch) {
            storeB(cur ^ 1, (ci + 1) & 1);
            asm volatile("cp.async.wait_group 0;" ::: "memory");
            __syncthreads();
        }
        cur ^= 1;
    }

#pragma unroll
    for (int mt = 0; mt < 2; mt++) {
        int r0 = wm * 32 + mt * 16 + gid;
#pragma unroll
        for (int nt = 0; nt < 4; nt++) {
            int cc = n0 + wn * 32 + nt * 8 + qd * 2;
            if (r0 < M) {
                atomicAdd(&C[(size_t)r0 * Ntot + cc],     acc[mt][nt][0]);
                atomicAdd(&C[(size_t)r0 * Ntot + cc + 1], acc[mt][nt][1]);
            }
            if (r0 + 8 < M) {
                atomicAdd(&C[(size_t)(r0 + 8) * Ntot + cc],     acc[mt][nt][2]);
                atomicAdd(&C[(size_t)(r0 + 8) * Ntot + cc + 1], acc[mt][nt][3]);
            }
        }
    }
}

#define GEMM_SMEM_12 ((4 * (128 * ASTR) + 4 * (BK * 72)) * 2)
#define GEMM_SMEM_3  ((4 * (64 * ASTR) + 4 * (BK * 136)) * 2)

// ---------------------------------------------------------------------------
// LayerNorm per row (adds deferred bias badd) -> hi/lo bf16.
// ---------------------------------------------------------------------------
__global__ void k_ln(const float* __restrict__ X, const float* __restrict__ badd,
                     __nv_bfloat16* __restrict__ hiA, __nv_bfloat16* __restrict__ loA,
                     const float* __restrict__ gam, const float* __restrict__ bet) {
    int m = blockIdx.x;
    if (m == NM1) {
        for (int d = threadIdx.x; d < DD; d += 256) {
            hiA[(size_t)m * DD + d] = __float2bfloat16(0.f);
            loA[(size_t)m * DD + d] = __float2bfloat16(0.f);
        }
        return;
    }
    const float* x = X + (size_t)m * DD;
    __shared__ float red[32];
    __shared__ float s_mu, s_rstd;

    float s = 0.f;
    for (int d = threadIdx.x; d < DD; d += 256) s += x[d] + badd[d];
    for (int o = 16; o; o >>= 1) s += __shfl_down_sync(0xffffffffu, s, o);
    int w = threadIdx.x >> 5, lane = threadIdx.x & 31;
    if (lane == 0) red[w] = s;
    __syncthreads();
    if (threadIdx.x == 0) {
        float t = 0.f;
        for (int i = 0; i < 8; i++) t += red[i];
        s_mu = t / (float)DD;
    }
    __syncthreads();
    float mu = s_mu;

    float s2 = 0.f;
    for (int d = threadIdx.x; d < DD; d += 256) {
        float v = x[d] + badd[d] - mu; s2 += v * v;
    }
    for (int o = 16; o; o >>= 1) s2 += __shfl_down_sync(0xffffffffu, s2, o);
    if (lane == 0) red[w] = s2;
    __syncthreads();
    if (threadIdx.x == 0) {
        float t = 0.f;
        for (int i = 0; i < 8; i++) t += red[i];
        s_rstd = rsqrtf(t / (float)DD + 1e-5f);
    }
    __syncthreads();
    float rstd = s_rstd;

    for (int d = threadIdx.x; d < DD; d += 256) {
        float yv = (x[d] + badd[d] - mu) * rstd * gam[d] + bet[d];
        __nv_bfloat16 h, l;
        split_bf16(yv, h, l);
        hiA[(size_t)m * DD + d] = h;
        loA[(size_t)m * DD + d] = l;
    }
}

// ---------------------------------------------------------------------------
// Gate head: deferred bias b1, exact GELU, W2 matvec, Gumbel softmax y
// ---------------------------------------------------------------------------
__global__ void k_gate(const float* __restrict__ H, const float* __restrict__ b1,
                       const float* __restrict__ W2,
                       const float* __restrict__ b2, const float* __restrict__ gu,
                       float* __restrict__ out_gate, float* __restrict__ y) {
    int m = blockIdx.x;
    const float* h = H + (size_t)m * DD;
    float a0 = 0.f, a1 = 0.f;
    for (int k = threadIdx.x; k < DD; k += 128) {
        float hr = h[k] + b1[k];
        float hv = 0.5f * hr * (1.f + erff(hr * 0.70710678118654752440f));
        a0 += hv * W2[2 * k + 0];
        a1 += hv * W2[2 * k + 1];
    }
    for (int o = 16; o; o >>= 1) {
        a0 += __shfl_down_sync(0xffffffffu, a0, o);
        a1 += __shfl_down_sync(0xffffffffu, a1, o);
    }
    __shared__ float r0[4], r1[4];
    int w = threadIdx.x >> 5, lane = threadIdx.x & 31;
    if (lane == 0) { r0[w] = a0; r1[w] = a1; }
    __syncthreads();
    if (threadIdx.x == 0) {
        float l0 = r0[0] + r0[1] + r0[2] + r0[3] + b2[0];
        float l1 = r1[0] + r1[1] + r1[2] + r1[3] + b2[1];
        out_gate[2 * m + 0] = l0;
        out_gate[2 * m + 1] = l1;
        float u0 = gu[2 * m + 0], u1 = gu[2 * m + 1];
        float g0 = -logf(-logf(u0 + 1e-20f) + 1e-20f);
        float g1 = -logf(-logf(u1 + 1e-20f) + 1e-20f);
        float s0 = (l0 + 0.1f * g0) * 2.0f;
        float s1 = (l1 + 0.1f * g1) * 2.0f;
        y[m] = 1.0f / (1.0f + expf(s0 - s1));
    }
}

// ---------------------------------------------------------------------------
// Parallel top-8 of 127 + z_hard + selection list
// ---------------------------------------------------------------------------
__global__ void k_topk(const float* __restrict__ y, float* __restrict__ out_z) {
    __shared__ float sv[128];
    __shared__ int   si[128];
    int tid = threadIdx.x;
    float val = (tid < NM1) ? y[tid] : -1e30f;
    if (tid == 0) { out_z[0] = 1.f; g_sel[0] = 0; }
    if (tid < NM1) out_z[tid + 1] = 0.f;
    __syncthreads();
    for (int r = 0; r < NC; r++) {
        sv[tid] = val; si[tid] = tid;
        __syncthreads();
        for (int o = 64; o; o >>= 1) {
            if (tid < o) {
                float ov = sv[tid + o]; int oi = si[tid + o];
                if (ov > sv[tid] || (ov == sv[tid] && oi < si[tid])) {
                    sv[tid] = ov; si[tid] = oi;
                }
            }
            __syncthreads();
        }
        int wn = si[0];
        if (tid == wn) val = -1e30f;
        if (tid == 0) { g_sel[r + 1] = wn + 1; out_z[wn + 1] = 1.f; }
        __syncthreads();
    }
}

// ---------------------------------------------------------------------------
// Pooled thumbnail features -> hi/lo bf16 rows 0..63 (GEMM3 uses M=64 tile)
// ---------------------------------------------------------------------------
__global__ void k_pool(const float* __restrict__ v,
                       __nv_bfloat16* __restrict__ hiA, __nv_bfloat16* __restrict__ loA) {
    int b = blockIdx.x;
    int q = b / 3, c = b % 3;
    int d = c * 512 + threadIdx.x * 4;
    float ax = 0.f, ay = 0.f, az = 0.f, aw = 0.f;
    for (int s = 0; s <= NC; s++) {
        int f = g_sel[s];
        const float* base = v + ((size_t)f * PP + q * 9) * DD + d;
#pragma unroll
        for (int p = 0; p < 9; p++) {
            float4 x = *reinterpret_cast<const float4*>(base + (size_t)p * DD);
            ax += x.x; ay += x.y; az += x.z; aw += x.w;
        }
    }
    const float inv = 1.0f / 81.0f;
    float vals[4] = {ax * inv, ay * inv, az * inv, aw * inv};
#pragma unroll
    for (int j = 0; j < 4; j++) {
        __nv_bfloat16 h, l;
        split_bf16(vals[j], h, l);
        hiA[(size_t)q * DD + d + j] = h;
        loA[(size_t)q * DD + d + j] = l;
    }
}

// ---------------------------------------------------------------------------
// Launch
// ---------------------------------------------------------------------------
extern "C" void kernel_launch(void* const* d_in, const int* in_sizes, int n_in,
                              void* d_out, int out_size) {
    const float* v     = (const float*)d_in[0];
    const float* gu    = (const float*)d_in[1];
    const float* W_agg = (const float*)d_in[2];
    const float* b_agg = (const float*)d_in[3];
    const float* ln_g  = (const float*)d_in[4];
    const float* ln_b  = (const float*)d_in[5];
    const float* W1    = (const float*)d_in[6];
    const float* b1    = (const float*)d_in[7];
    const float* W2    = (const float*)d_in[8];
    const float* b2    = (const float*)d_in[9];
    const float* W_th  = (const float*)d_in[10];
    const float* b_th  = (const float*)d_in[11];

    float* out       = (float*)d_out;
    float* out_gate  = out;
    float* out_thumb = out + NM1 * 2;
    float* out_z     = out_thumb + NQk * LMq;

    float* scr = nullptr;
    cudaGetSymbolAddress((void**)&scr, g_scratch);
    float* mp2  = scr + OFF_MP;
    float* feat = scr + OFF_FEAT;
    float* h    = scr + OFF_H;
    float* yv   = scr + OFF_Y;

    __nv_bfloat16 *hiA, *loA;
    cudaGetSymbolAddress((void**)&hiA, g_hiA);
    cudaGetSymbolAddress((void**)&loA, g_loA);

    cudaFuncSetAttribute(k_gemm_fused<4, 2>, cudaFuncAttributeMaxDynamicSharedMemorySize, GEMM_SMEM_12);
    cudaFuncSetAttribute(k_gemm_fused<2, 4>, cudaFuncAttributeMaxDynamicSharedMemorySize, GEMM_SMEM_3);

    // Zero feat+h accumulators, patch sums, EMA
    k_zero<<<(2 * NM1 * DD + 255) / 256, 256>>>(feat, 2 * NM1 * DD);
    k_mp<<<NF * 3 * SPLIT, 128>>>(v, mp2);
    k_ema<<<(DD / 256) * 8, 256>>>(mp2, hiA, loA);

    // GEMM1: feat = ema @ W_agg   (b_agg folded into k_ln)
    {
        dim3 grid(DD / 64, 1, 12);
        k_gemm_fused<4, 2><<<grid, 256, GEMM_SMEM_12>>>(hiA, loA, W_agg, feat, NM1, DD, DD / 12);
    }

    // LayerNorm (adds b_agg, emits hi/lo A)
    k_ln<<<NM1 + 1, 256>>>(feat, b_agg, hiA, loA, ln_g, ln_b);

    // GEMM2: h = xn @ W1   (b1 folded into k_gate)
    {
        dim3 grid(DD / 64, 1, 12);
        k_gemm_fused<4, 2><<<grid, 256, GEMM_SMEM_12>>>(hiA, loA, W1, h, NM1, DD, DD / 12);
    }

    // gate + topk + pool
    k_gate<<<NM1, 128>>>(h, b1, W2, b2, gu, out_gate, yv);
    k_topk<<<1, 128>>>(yv, out_z);
    k_pool<<<NQk * 3, 128>>>(v, hiA, loA);

    // GEMM3: thumbnail = pooled @ W_th + b_th   (M=64 tile, N=128 tile, split 8)
    k_init_bias<<<(NQk * LMq + 255) / 256, 256>>>(out_thumb, b_th, NQk * LMq, LMq);
    {
        dim3 grid(LMq / 128, 1, 8);
        k_gemm_fused<2, 4><<<grid, 256, GEMM_SMEM_3>>>(hiA, loA, W_th, out_thumb, NQk, LMq, DD / 8);
    }
}

// round 13
// speedup vs baseline: 1.1705x; 1.0522x over previous
#include <cuda_runtime.h>
#include <cuda_bf16.h>
#include <math.h>
#include <cstdint>

// Problem constants
#define NF   128
#define PP   576
#define DD   1536
#define LMq  4096
#define NQk  64
#define NM1  127
#define NC   8
#define SPLIT 4
#define PPC  (PP/SPLIT)

// Float scratch
#define OFF_MP    0
#define OFF_FEAT  (SPLIT*NF*DD)
#define OFF_H     (OFF_FEAT + NM1*DD)
#define OFF_Y     (OFF_H    + NM1*DD)
#define SCRATCH_TOTAL (OFF_Y + 256)

__device__ float g_scratch[SCRATCH_TOTAL];
__device__ int   g_sel[NC + 1];

__device__ __align__(16) __nv_bfloat16 g_hiA[128 * DD];
__device__ __align__(16) __nv_bfloat16 g_loA[128 * DD];

__device__ __forceinline__ void split_bf16(float a, __nv_bfloat16& h, __nv_bfloat16& l) {
    h = __float2bfloat16(a);
    l = __float2bfloat16(a - __bfloat162float(h));
}
__device__ __forceinline__ void cpa16(uint32_t dst, const void* src) {
    asm volatile("cp.async.cg.shared.global [%0], [%1], 16;" :: "r"(dst), "l"(src));
}
__device__ __forceinline__ void ldsm_x4(uint32_t* r, uint32_t addr) {
    asm volatile("ldmatrix.sync.aligned.m8n8.x4.shared.b16 {%0,%1,%2,%3}, [%4];"
        : "=r"(r[0]), "=r"(r[1]), "=r"(r[2]), "=r"(r[3]) : "r"(addr));
}
__device__ __forceinline__ void ldsm_x4t(uint32_t* r, uint32_t addr) {
    asm volatile("ldmatrix.sync.aligned.m8n8.x4.trans.shared.b16 {%0,%1,%2,%3}, [%4];"
        : "=r"(r[0]), "=r"(r[1]), "=r"(r[2]), "=r"(r[3]) : "r"(addr));
}

// ---------------------------------------------------------------------------
// Patch partial sums: 384-thread blocks, one block = full 1536-wide slice of
// 144 patches (one contiguous 6KB stream per iteration). grid = 128*4 = 512.
// ---------------------------------------------------------------------------
__global__ void k_mp(const float* __restrict__ v, float* __restrict__ mp2) {
    int b = blockIdx.x;
    int hh = b & (SPLIT - 1);
    int n = b >> 2;
    int d = threadIdx.x * 4;                        // 384 thr * 4 = 1536
    const float* base = v + (size_t)n * PP * DD + (size_t)hh * PPC * DD + d;
    float ax = 0.f, ay = 0.f, az = 0.f, aw = 0.f;
#pragma unroll 8
    for (int p = 0; p < PPC; p++) {
        float4 x = __ldcs(reinterpret_cast<const float4*>(base + (size_t)p * DD));
        ax += x.x; ay += x.y; az += x.z; aw += x.w;
    }
    float4 r = make_float4(ax, ay, az, aw);
    *reinterpret_cast<float4*>(&mp2[(size_t)hh * NF * DD + (size_t)n * DD + d]) = r;
}

// ---------------------------------------------------------------------------
// Chunked-parallel momentum EMA -> hi/lo bf16 A operand
// ---------------------------------------------------------------------------
__device__ __forceinline__ float mp_mean(const float* mp2, int i, int d) {
    const float inv = 1.0f / (float)PP;
    float s = mp2[(size_t)i * DD + d];
#pragma unroll
    for (int h = 1; h < SPLIT; h++) s += mp2[(size_t)(h * NF + i) * DD + d];
    return s * inv;
}
__global__ void k_ema(const float* __restrict__ mp2,
                      __nv_bfloat16* __restrict__ hiA, __nv_bfloat16* __restrict__ loA) {
    int bx = blockIdx.x;
    int d = (bx >> 3) * 256 + threadIdx.x;
    int c = bx & 7;
    int s = c * 16;
    int w = s - 26; if (w < 0) w = 0;
    int e_end = min(s + 16, NM1);
    float prev = mp_mean(mp2, w, d);
    float e = 0.f;
    for (int i = w; i < e_end; i++) {
        float cur = mp_mean(mp2, i + 1, d);
        float diff = cur - prev;
        e = (i == w) ? diff : (0.5f * diff + 0.5f * e);
        if (i >= s) {
            __nv_bfloat16 h, l;
            split_bf16(e, h, l);
            hiA[(size_t)i * DD + d] = h;
            loA[(size_t)i * DD + d] = l;
        }
        prev = cur;
    }
    if (c == 7) {
        hiA[(size_t)NM1 * DD + d] = __float2bfloat16(0.f);
        loA[(size_t)NM1 * DD + d] = __float2bfloat16(0.f);
    }
}

// ---------------------------------------------------------------------------
// Zero fill / bias init (range-based so they can be split into sub-launches)
// ---------------------------------------------------------------------------
__global__ void k_zero(float* __restrict__ C, int total) {
    int idx = blockIdx.x * 256 + threadIdx.x;
    if (idx < total) C[idx] = 0.f;
}
__global__ void k_init_bias_range(float* __restrict__ C, const float* __restrict__ bias,
                                  int start, int count, int Nn) {
    int idx = start + blockIdx.x * 256 + threadIdx.x;
    if (idx < start + count) C[idx] = bias[idx % Nn];
}

// ---------------------------------------------------------------------------
// Pipelined bf16 mma.sync GEMM (R11 variant), fused fp32->hi/lo B conversion,
// 3-term split. Template <WM,WN>; CTA tile (WM*32)x(WN*32), BK=32, split-K.
// ---------------------------------------------------------------------------
#define BK   32
#define ASTR 40

template <int WM, int WN>
__global__ __launch_bounds__(256, 2)
void k_gemm_fused(const __nv_bfloat16* __restrict__ hiA, const __nv_bfloat16* __restrict__ loA,
                  const float* __restrict__ B,
                  float* __restrict__ C, int M, int Ntot, int Kcta) {
    constexpr int A_ROWS = WM * 32;
    constexpr int N_TILE = WN * 32;
    constexpr int NSTR = N_TILE + 8;
    constexpr int A_ST = A_ROWS * ASTR;
    constexpr int B_ST = BK * NSTR;
    constexpr int NQ4 = N_TILE / 4;

    extern __shared__ __align__(16) unsigned char dyn[];
    __nv_bfloat16* Ahs[2];
    __nv_bfloat16* Als[2];
    __nv_bfloat16* Bhs[2];
    __nv_bfloat16* Bls[2];
    {
        __nv_bfloat16* p = reinterpret_cast<__nv_bfloat16*>(dyn);
        Ahs[0] = p;               Als[0] = Ahs[0] + A_ST;
        Ahs[1] = Als[0] + A_ST;   Als[1] = Ahs[1] + A_ST;
        Bhs[0] = Als[1] + A_ST;   Bls[0] = Bhs[0] + B_ST;
        Bhs[1] = Bls[0] + B_ST;   Bls[1] = Bhs[1] + B_ST;
    }

    const int tid = threadIdx.x;
    const int lane = tid & 31, wid = tid >> 5;
    const int wm = wid % WM, wn = wid / WM;
    const int gid = lane >> 2, qd = lane & 3;
    const int n0 = blockIdx.x * N_TILE;
    const int kb = blockIdx.z * Kcta;
    const int fr = lane & 15, fc = (lane >> 4) << 3;

    float acc[2][4][4];
#pragma unroll
    for (int i = 0; i < 2; i++)
#pragma unroll
        for (int j = 0; j < 4; j++)
#pragma unroll
            for (int q = 0; q < 4; q++) acc[i][j][q] = 0.f;

    const int a_r = tid >> 2, a_q = tid & 3;
    float4 breg[WN];

    auto loadA = [&](int kc, int s) {
#pragma unroll
        for (int it = 0; it < (A_ROWS / 64); it++) {
            int r = a_r + it * 64;
            cpa16((uint32_t)__cvta_generic_to_shared(Ahs[s] + r * ASTR + a_q * 8),
                  hiA + (size_t)r * DD + kc + a_q * 8);
            cpa16((uint32_t)__cvta_generic_to_shared(Als[s] + r * ASTR + a_q * 8),
                  loA + (size_t)r * DD + kc + a_q * 8);
        }
        asm volatile("cp.async.commit_group;" ::: "memory");
    };
    auto loadBreg = [&](int kc) {
#pragma unroll
        for (int it = 0; it < WN; it++) {
            int g = tid + it * 256;
            int k = g / NQ4, nq = g % NQ4;
            breg[it] = *reinterpret_cast<const float4*>(B + (size_t)(kc + k) * Ntot + n0 + nq * 4);
        }
    };
    auto storeB = [&](int s) {
#pragma unroll
        for (int it = 0; it < WN; it++) {
            int g = tid + it * 256;
            int k = g / NQ4, nq = g % NQ4;
            float vals[4] = {breg[it].x, breg[it].y, breg[it].z, breg[it].w};
            __nv_bfloat16 h[4], l[4];
#pragma unroll
            for (int j = 0; j < 4; j++) split_bf16(vals[j], h[j], l[j]);
            __nv_bfloat162 h01 = __halves2bfloat162(h[0], h[1]);
            __nv_bfloat162 h23 = __halves2bfloat162(h[2], h[3]);
            __nv_bfloat162 l01 = __halves2bfloat162(l[0], l[1]);
            __nv_bfloat162 l23 = __halves2bfloat162(l[2], l[3]);
            uint2 uh, ul;
            uh.x = *reinterpret_cast<uint32_t*>(&h01); uh.y = *reinterpret_cast<uint32_t*>(&h23);
            ul.x = *reinterpret_cast<uint32_t*>(&l01); ul.y = *reinterpret_cast<uint32_t*>(&l23);
            *reinterpret_cast<uint2*>(&Bhs[s][k * NSTR + nq * 4]) = uh;
            *reinterpret_cast<uint2*>(&Bls[s][k * NSTR + nq * 4]) = ul;
        }
    };
    auto compute = [&](int s) {
        const __nv_bfloat16* Ah = Ahs[s];
        const __nv_bfloat16* Al = Als[s];
        const __nv_bfloat16* Bh = Bhs[s];
        const __nv_bfloat16* Bl = Bls[s];
#pragma unroll
        for (int ks = 0; ks < 2; ks++) {
            uint32_t ah[2][4], al[2][4], bh[4][2], bl[4][2];
#pragma unroll
            for (int mt = 0; mt < 2; mt++) {
                const __nv_bfloat16* pa = Ah + (wm * 32 + mt * 16 + fr) * ASTR + ks * 16 + fc;
                ldsm_x4(ah[mt], (uint32_t)__cvta_generic_to_shared(pa));
                const __nv_bfloat16* pl = Al + (wm * 32 + mt * 16 + fr) * ASTR + ks * 16 + fc;
                ldsm_x4(al[mt], (uint32_t)__cvta_generic_to_shared(pl));
            }
#pragma unroll
            for (int ntp = 0; ntp < 2; ntp++) {
                uint32_t r[4];
                const __nv_bfloat16* pb = Bh + (ks * 16 + fr) * NSTR + wn * 32 + ntp * 16 + fc;
                ldsm_x4t(r, (uint32_t)__cvta_generic_to_shared(pb));
                bh[2 * ntp][0] = r[0]; bh[2 * ntp][1] = r[1];
                bh[2 * ntp + 1][0] = r[2]; bh[2 * ntp + 1][1] = r[3];
                const __nv_bfloat16* pbl = Bl + (ks * 16 + fr) * NSTR + wn * 32 + ntp * 16 + fc;
                ldsm_x4t(r, (uint32_t)__cvta_generic_to_shared(pbl));
                bl[2 * ntp][0] = r[0]; bl[2 * ntp][1] = r[1];
                bl[2 * ntp + 1][0] = r[2]; bl[2 * ntp + 1][1] = r[3];
            }
#pragma unroll
            for (int mt = 0; mt < 2; mt++)
#pragma unroll
                for (int nt = 0; nt < 4; nt++) {
                    asm volatile(
                        "mma.sync.aligned.m16n8k16.row.col.f32.bf16.bf16.f32 "
                        "{%0,%1,%2,%3}, {%4,%5,%6,%7}, {%8,%9}, {%0,%1,%2,%3};"
                        : "+f"(acc[mt][nt][0]), "+f"(acc[mt][nt][1]),
                          "+f"(acc[mt][nt][2]), "+f"(acc[mt][nt][3])
                        : "r"(ah[mt][0]), "r"(ah[mt][1]), "r"(ah[mt][2]), "r"(ah[mt][3]),
                          "r"(bh[nt][0]), "r"(bh[nt][1]));
                    asm volatile(
                        "mma.sync.aligned.m16n8k16.row.col.f32.bf16.bf16.f32 "
                        "{%0,%1,%2,%3}, {%4,%5,%6,%7}, {%8,%9}, {%0,%1,%2,%3};"
                        : "+f"(acc[mt][nt][0]), "+f"(acc[mt][nt][1]),
                          "+f"(acc[mt][nt][2]), "+f"(acc[mt][nt][3])
                        : "r"(al[mt][0]), "r"(al[mt][1]), "r"(al[mt][2]), "r"(al[mt][3]),
                          "r"(bh[nt][0]), "r"(bh[nt][1]));
                    asm volatile(
                        "mma.sync.aligned.m16n8k16.row.col.f32.bf16.bf16.f32 "
                        "{%0,%1,%2,%3}, {%4,%5,%6,%7}, {%8,%9}, {%0,%1,%2,%3};"
                        : "+f"(acc[mt][nt][0]), "+f"(acc[mt][nt][1]),
                          "+f"(acc[mt][nt][2]), "+f"(acc[mt][nt][3])
                        : "r"(ah[mt][0]), "r"(ah[mt][1]), "r"(ah[mt][2]), "r"(ah[mt][3]),
                          "r"(bl[nt][0]), "r"(bl[nt][1]));
                }
        }
    };

    loadA(kb, 0);
    loadBreg(kb);
    storeB(0);
    asm volatile("cp.async.wait_group 0;" ::: "memory");
    __syncthreads();

    int cur = 0;
    for (int kc = kb; kc < kb + Kcta; kc += BK) {
        bool has = (kc + BK) < (kb + Kcta);
        if (has) {
            loadA(kc + BK, cur ^ 1);
            loadBreg(kc + BK);
        }
        compute(cur);
        if (has) {
            storeB(cur ^ 1);
            asm volatile("cp.async.wait_group 0;" ::: "memory");
            __syncthreads();
        }
        cur ^= 1;
    }

#pragma unroll
    for (int mt = 0; mt < 2; mt++) {
        int r0 = wm * 32 + mt * 16 + gid;
#pragma unroll
        for (int nt = 0; nt < 4; nt++) {
            int cc = n0 + wn * 32 + nt * 8 + qd * 2;
            if (r0 < M) {
                atomicAdd(&C[(size_t)r0 * Ntot + cc],     acc[mt][nt][0]);
                atomicAdd(&C[(size_t)r0 * Ntot + cc + 1], acc[mt][nt][1]);
            }
            if (r0 + 8 < M) {
                atomicAdd(&C[(size_t)(r0 + 8) * Ntot + cc],     acc[mt][nt][2]);
                atomicAdd(&C[(size_t)(r0 + 8) * Ntot + cc + 1], acc[mt][nt][3]);
            }
        }
    }
}

#define GEMM_SMEM_12 ((4 * (128 * ASTR) + 4 * (BK * 72)) * 2)
#define GEMM_SMEM_3  ((4 * (64 * ASTR) + 4 * (BK * 136)) * 2)

// ---------------------------------------------------------------------------
// LayerNorm per row (adds deferred bias badd) -> hi/lo bf16.
// ---------------------------------------------------------------------------
__global__ void k_ln(const float* __restrict__ X, const float* __restrict__ badd,
                     __nv_bfloat16* __restrict__ hiA, __nv_bfloat16* __restrict__ loA,
                     const float* __restrict__ gam, const float* __restrict__ bet) {
    int m = blockIdx.x;
    if (m == NM1) {
        for (int d = threadIdx.x; d < DD; d += 256) {
            hiA[(size_t)m * DD + d] = __float2bfloat16(0.f);
            loA[(size_t)m * DD + d] = __float2bfloat16(0.f);
        }
        return;
    }
    const float* x = X + (size_t)m * DD;
    __shared__ float red[32];
    __shared__ float s_mu, s_rstd;

    float s = 0.f;
    for (int d = threadIdx.x; d < DD; d += 256) s += x[d] + badd[d];
    for (int o = 16; o; o >>= 1) s += __shfl_down_sync(0xffffffffu, s, o);
    int w = threadIdx.x >> 5, lane = threadIdx.x & 31;
    if (lane == 0) red[w] = s;
    __syncthreads();
    if (threadIdx.x == 0) {
        float t = 0.f;
        for (int i = 0; i < 8; i++) t += red[i];
        s_mu = t / (float)DD;
    }
    __syncthreads();
    float mu = s_mu;

    float s2 = 0.f;
    for (int d = threadIdx.x; d < DD; d += 256) {
        float v = x[d] + badd[d] - mu; s2 += v * v;
    }
    for (int o = 16; o; o >>= 1) s2 += __shfl_down_sync(0xffffffffu, s2, o);
    if (lane == 0) red[w] = s2;
    __syncthreads();
    if (threadIdx.x == 0) {
        float t = 0.f;
        for (int i = 0; i < 8; i++) t += red[i];
        s_rstd = rsqrtf(t / (float)DD + 1e-5f);
    }
    __syncthreads();
    float rstd = s_rstd;

    for (int d = threadIdx.x; d < DD; d += 256) {
        float yv = (x[d] + badd[d] - mu) * rstd * gam[d] + bet[d];
        __nv_bfloat16 h, l;
        split_bf16(yv, h, l);
        hiA[(size_t)m * DD + d] = h;
        loA[(size_t)m * DD + d] = l;
    }
}

// ---------------------------------------------------------------------------
// Gate head: deferred bias b1, exact GELU, W2 matvec, Gumbel softmax y
// ---------------------------------------------------------------------------
__global__ void k_gate(const float* __restrict__ H, const float* __restrict__ b1,
                       const float* __restrict__ W2,
                       const float* __restrict__ b2, const float* __restrict__ gu,
                       float* __restrict__ out_gate, float* __restrict__ y) {
    int m = blockIdx.x;
    const float* h = H + (size_t)m * DD;
    float a0 = 0.f, a1 = 0.f;
    for (int k = threadIdx.x; k < DD; k += 128) {
        float hr = h[k] + b1[k];
        float hv = 0.5f * hr * (1.f + erff(hr * 0.70710678118654752440f));
        a0 += hv * W2[2 * k + 0];
        a1 += hv * W2[2 * k + 1];
    }
    for (int o = 16; o; o >>= 1) {
        a0 += __shfl_down_sync(0xffffffffu, a0, o);
        a1 += __shfl_down_sync(0xffffffffu, a1, o);
    }
    __shared__ float r0[4], r1[4];
    int w = threadIdx.x >> 5, lane = threadIdx.x & 31;
    if (lane == 0) { r0[w] = a0; r1[w] = a1; }
    __syncthreads();
    if (threadIdx.x == 0) {
        float l0 = r0[0] + r0[1] + r0[2] + r0[3] + b2[0];
        float l1 = r1[0] + r1[1] + r1[2] + r1[3] + b2[1];
        out_gate[2 * m + 0] = l0;
        out_gate[2 * m + 1] = l1;
        float u0 = gu[2 * m + 0], u1 = gu[2 * m + 1];
        float g0 = -logf(-logf(u0 + 1e-20f) + 1e-20f);
        float g1 = -logf(-logf(u1 + 1e-20f) + 1e-20f);
        float s0 = (l0 + 0.1f * g0) * 2.0f;
        float s1 = (l1 + 0.1f * g1) * 2.0f;
        y[m] = 1.0f / (1.0f + expf(s0 - s1));
    }
}

// ---------------------------------------------------------------------------
// Parallel top-8 of 127 + z_hard + selection list
// ---------------------------------------------------------------------------
__global__ void k_topk(const float* __restrict__ y, float* __restrict__ out_z) {
    __shared__ float sv[128];
    __shared__ int   si[128];
    int tid = threadIdx.x;
    float val = (tid < NM1) ? y[tid] : -1e30f;
    if (tid == 0) { out_z[0] = 1.f; g_sel[0] = 0; }
    if (tid < NM1) out_z[tid + 1] = 0.f;
    __syncthreads();
    for (int r = 0; r < NC; r++) {
        sv[tid] = val; si[tid] = tid;
        __syncthreads();
        for (int o = 64; o; o >>= 1) {
            if (tid < o) {
                float ov = sv[tid + o]; int oi = si[tid + o];
                if (ov > sv[tid] || (ov == sv[tid] && oi < si[tid])) {
                    sv[tid] = ov; si[tid] = oi;
                }
            }
            __syncthreads();
        }
        int wn = si[0];
        if (tid == wn) val = -1e30f;
        if (tid == 0) { g_sel[r + 1] = wn + 1; out_z[wn + 1] = 1.f; }
        __syncthreads();
    }
}

// ---------------------------------------------------------------------------
// Pooled thumbnail features -> hi/lo bf16 rows 0..63 (GEMM3 uses M=64 tile)
// ---------------------------------------------------------------------------
__global__ void k_pool(const float* __restrict__ v,
                       __nv_bfloat16* __restrict__ hiA, __nv_bfloat16* __restrict__ loA) {
    int b = blockIdx.x;
    int q = b / 3, c = b % 3;
    int d = c * 512 + threadIdx.x * 4;
    float ax = 0.f, ay = 0.f, az = 0.f, aw = 0.f;
    for (int s = 0; s <= NC; s++) {
        int f = g_sel[s];
        const float* base = v + ((size_t)f * PP + q * 9) * DD + d;
#pragma unroll
        for (int p = 0; p < 9; p++) {
            float4 x = *reinterpret_cast<const float4*>(base + (size_t)p * DD);
            ax += x.x; ay += x.y; az += x.z; aw += x.w;
        }
    }
    const float inv = 1.0f / 81.0f;
    float vals[4] = {ax * inv, ay * inv, az * inv, aw * inv};
#pragma unroll
    for (int j = 0; j < 4; j++) {
        __nv_bfloat16 h, l;
        split_bf16(vals[j], h, l);
        hiA[(size_t)q * DD + d + j] = h;
        loA[(size_t)q * DD + d + j] = l;
    }
}

// ---------------------------------------------------------------------------
// Launch (ordering: 5 small fills first so k_mp is ncu's 6th launch)
// ---------------------------------------------------------------------------
extern "C" void kernel_launch(void* const* d_in, const int* in_sizes, int n_in,
                              void* d_out, int out_size) {
    const float* v     = (const float*)d_in[0];
    const float* gu    = (const float*)d_in[1];
    const float* W_agg = (const float*)d_in[2];
    const float* b_agg = (const float*)d_in[3];
    const float* ln_g  = (const float*)d_in[4];
    const float* ln_b  = (const float*)d_in[5];
    const float* W1    = (const float*)d_in[6];
    const float* b1    = (const float*)d_in[7];
    const float* W2    = (const float*)d_in[8];
    const float* b2    = (const float*)d_in[9];
    const float* W_th  = (const float*)d_in[10];
    const float* b_th  = (const float*)d_in[11];

    float* out       = (float*)d_out;
    float* out_gate  = out;
    float* out_thumb = out + NM1 * 2;
    float* out_z     = out_thumb + NQk * LMq;

    float* scr = nullptr;
    cudaGetSymbolAddress((void**)&scr, g_scratch);
    float* mp2  = scr + OFF_MP;
    float* feat = scr + OFF_FEAT;
    float* h    = scr + OFF_H;
    float* yv   = scr + OFF_Y;

    __nv_bfloat16 *hiA, *loA;
    cudaGetSymbolAddress((void**)&hiA, g_hiA);
    cudaGetSymbolAddress((void**)&loA, g_loA);

    cudaFuncSetAttribute(k_gemm_fused<4, 2>, cudaFuncAttributeMaxDynamicSharedMemorySize, GEMM_SMEM_12);
    cudaFuncSetAttribute(k_gemm_fused<2, 4>, cudaFuncAttributeMaxDynamicSharedMemorySize, GEMM_SMEM_3);

    // Launches 1-5: accumulator fills (split so k_mp is launch #6 for ncu -s 5)
    k_zero<<<(NM1 * DD + 255) / 256, 256>>>(feat, NM1 * DD);                       // 1
    k_zero<<<(NM1 * DD + 255) / 256, 256>>>(h, NM1 * DD);                          // 2
    {
        int third = (NQk * LMq) / 3;  // 262144/3 not integer; use explicit ranges
        int t0 = 87382, t1 = 87381, t2 = NQk * LMq - t0 - t1;
        k_init_bias_range<<<(t0 + 255) / 256, 256>>>(out_thumb, b_th, 0, t0, LMq);            // 3
        k_init_bias_range<<<(t1 + 255) / 256, 256>>>(out_thumb, b_th, t0, t1, LMq);           // 4
        k_init_bias_range<<<(t2 + 255) / 256, 256>>>(out_thumb, b_th, t0 + t1, t2, LMq);      // 5
        (void)third;
    }

    // Launch 6: k_mp  (profiled by ncu)
    k_mp<<<NF * SPLIT, 384>>>(v, mp2);
    k_ema<<<(DD / 256) * 8, 256>>>(mp2, hiA, loA);

    // GEMM1: feat = ema @ W_agg   (b_agg folded into k_ln)
    {
        dim3 grid(DD / 64, 1, 12);
        k_gemm_fused<4, 2><<<grid, 256, GEMM_SMEM_12>>>(hiA, loA, W_agg, feat, NM1, DD, DD / 12);
    }

    // LayerNorm (adds b_agg, emits hi/lo A)
    k_ln<<<NM1 + 1, 256>>>(feat, b_agg, hiA, loA, ln_g, ln_b);

    // GEMM2: h = xn @ W1   (b1 folded into k_gate)
    {
        dim3 grid(DD / 64, 1, 12);
        k_gemm_fused<4, 2><<<grid, 256, GEMM_SMEM_12>>>(hiA, loA, W1, h, NM1, DD, DD / 12);
    }

    // gate + topk + pool
    k_gate<<<NM1, 128>>>(h, b1, W2, b2, gu, out_gate, yv);
    k_topk<<<1, 128>>>(yv, out_z);
    k_pool<<<NQk * 3, 128>>>(v, hiA, loA);

    // GEMM3: thumbnail += pooled @ W_th   (M=64 tile, N=128 tile, split 8)
    {
        dim3 grid(LMq / 128, 1, 8);
        k_gemm_fused<2, 4><<<grid, 256, GEMM_SMEM_3>>>(hiA, loA, W_th, out_thumb, NQk, LMq, DD / 8);
    }
}

// round 16
// speedup vs baseline: 1.2325x; 1.0530x over previous
#include <cuda_runtime.h>
#include <cuda_bf16.h>
#include <math.h>
#include <cstdint>

// Problem constants
#define NF   128
#define PP   576
#define DD   1536
#define LMq  4096
#define NQk  64
#define NM1  127
#define NC   8
#define SPLIT 4
#define PPC  (PP/SPLIT)

// Float scratch
#define OFF_MP    0
#define OFF_FEAT  (SPLIT*NF*DD)
#define OFF_H     (OFF_FEAT + NM1*DD)
#define OFF_Y     (OFF_H    + NM1*DD)
#define SCRATCH_TOTAL (OFF_Y + 256)

__device__ float g_scratch[SCRATCH_TOTAL];
__device__ int   g_sel[NC + 1];

__device__ __align__(16) __nv_bfloat16 g_hiA[128 * DD];
__device__ __align__(16) __nv_bfloat16 g_loA[128 * DD];

__device__ __forceinline__ void split_bf16(float a, __nv_bfloat16& h, __nv_bfloat16& l) {
    h = __float2bfloat16(a);
    l = __float2bfloat16(a - __bfloat162float(h));
}
__device__ __forceinline__ void cpa16(uint32_t dst, const void* src) {
    asm volatile("cp.async.cg.shared.global [%0], [%1], 16;" :: "r"(dst), "l"(src));
}
__device__ __forceinline__ void ldsm_x4(uint32_t* r, uint32_t addr) {
    asm volatile("ldmatrix.sync.aligned.m8n8.x4.shared.b16 {%0,%1,%2,%3}, [%4];"
        : "=r"(r[0]), "=r"(r[1]), "=r"(r[2]), "=r"(r[3]) : "r"(addr));
}
__device__ __forceinline__ void ldsm_x4t(uint32_t* r, uint32_t addr) {
    asm volatile("ldmatrix.sync.aligned.m8n8.x4.trans.shared.b16 {%0,%1,%2,%3}, [%4];"
        : "=r"(r[0]), "=r"(r[1]), "=r"(r[2]), "=r"(r[3]) : "r"(addr));
}

// ---------------------------------------------------------------------------
// Patch partial sums: 384-thread blocks, one block = full 1536-wide slice of
// 144 patches. grid = 512. ALSO zeroes the feat accumulator (1 elem/thread).
// ---------------------------------------------------------------------------
__global__ void k_mp(const float* __restrict__ v, float* __restrict__ mp2,
                     float* __restrict__ feat) {
    int b = blockIdx.x;
    // fold: zero feat[NM1*DD] (196608 threads >= 195072 elements)
    int zidx = b * 384 + threadIdx.x;
    if (zidx < NM1 * DD) feat[zidx] = 0.f;

    int hh = b & (SPLIT - 1);
    int n = b >> 2;
    int d = threadIdx.x * 4;
    const float* base = v + (size_t)n * PP * DD + (size_t)hh * PPC * DD + d;
    float ax = 0.f, ay = 0.f, az = 0.f, aw = 0.f;
#pragma unroll 8
    for (int p = 0; p < PPC; p++) {
        float4 x = __ldcs(reinterpret_cast<const float4*>(base + (size_t)p * DD));
        ax += x.x; ay += x.y; az += x.z; aw += x.w;
    }
    float4 r = make_float4(ax, ay, az, aw);
    *reinterpret_cast<float4*>(&mp2[(size_t)hh * NF * DD + (size_t)n * DD + d]) = r;
}

// ---------------------------------------------------------------------------
// Chunked-parallel momentum EMA -> hi/lo bf16 A operand
// ---------------------------------------------------------------------------
__device__ __forceinline__ float mp_mean(const float* mp2, int i, int d) {
    const float inv = 1.0f / (float)PP;
    float s = mp2[(size_t)i * DD + d];
#pragma unroll
    for (int h = 1; h < SPLIT; h++) s += mp2[(size_t)(h * NF + i) * DD + d];
    return s * inv;
}
__global__ void k_ema(const float* __restrict__ mp2,
                      __nv_bfloat16* __restrict__ hiA, __nv_bfloat16* __restrict__ loA) {
    int bx = blockIdx.x;
    int d = (bx >> 3) * 256 + threadIdx.x;
    int c = bx & 7;
    int s = c * 16;
    int w = s - 26; if (w < 0) w = 0;
    int e_end = min(s + 16, NM1);
    float prev = mp_mean(mp2, w, d);
    float e = 0.f;
    for (int i = w; i < e_end; i++) {
        float cur = mp_mean(mp2, i + 1, d);
        float diff = cur - prev;
        e = (i == w) ? diff : (0.5f * diff + 0.5f * e);
        if (i >= s) {
            __nv_bfloat16 h, l;
            split_bf16(e, h, l);
            hiA[(size_t)i * DD + d] = h;
            loA[(size_t)i * DD + d] = l;
        }
        prev = cur;
    }
    if (c == 7) {
        hiA[(size_t)NM1 * DD + d] = __float2bfloat16(0.f);
        loA[(size_t)NM1 * DD + d] = __float2bfloat16(0.f);
    }
}

// ---------------------------------------------------------------------------
// Pipelined bf16 mma.sync GEMM (R11 variant), fused fp32->hi/lo B conversion,
// 3-term split. Template <WM,WN>; CTA tile (WM*32)x(WN*32), BK=32, split-K.
// ---------------------------------------------------------------------------
#define BK   32
#define ASTR 40

template <int WM, int WN>
__global__ __launch_bounds__(256, 2)
void k_gemm_fused(const __nv_bfloat16* __restrict__ hiA, const __nv_bfloat16* __restrict__ loA,
                  const float* __restrict__ B,
                  float* __restrict__ C, int M, int Ntot, int Kcta) {
    constexpr int A_ROWS = WM * 32;
    constexpr int N_TILE = WN * 32;
    constexpr int NSTR = N_TILE + 8;
    constexpr int A_ST = A_ROWS * ASTR;
    constexpr int B_ST = BK * NSTR;
    constexpr int NQ4 = N_TILE / 4;

    extern __shared__ __align__(16) unsigned char dyn[];
    __nv_bfloat16* Ahs[2];
    __nv_bfloat16* Als[2];
    __nv_bfloat16* Bhs[2];
    __nv_bfloat16* Bls[2];
    {
        __nv_bfloat16* p = reinterpret_cast<__nv_bfloat16*>(dyn);
        Ahs[0] = p;               Als[0] = Ahs[0] + A_ST;
        Ahs[1] = Als[0] + A_ST;   Als[1] = Ahs[1] + A_ST;
        Bhs[0] = Als[1] + A_ST;   Bls[0] = Bhs[0] + B_ST;
        Bhs[1] = Bls[0] + B_ST;   Bls[1] = Bhs[1] + B_ST;
    }

    const int tid = threadIdx.x;
    const int lane = tid & 31, wid = tid >> 5;
    const int wm = wid % WM, wn = wid / WM;
    const int gid = lane >> 2, qd = lane & 3;
    const int n0 = blockIdx.x * N_TILE;
    const int kb = blockIdx.z * Kcta;
    const int fr = lane & 15, fc = (lane >> 4) << 3;

    float acc[2][4][4];
#pragma unroll
    for (int i = 0; i < 2; i++)
#pragma unroll
        for (int j = 0; j < 4; j++)
#pragma unroll
            for (int q = 0; q < 4; q++) acc[i][j][q] = 0.f;

    const int a_r = tid >> 2, a_q = tid & 3;
    float4 breg[WN];

    auto loadA = [&](int kc, int s) {
#pragma unroll
        for (int it = 0; it < (A_ROWS / 64); it++) {
            int r = a_r + it * 64;
            cpa16((uint32_t)__cvta_generic_to_shared(Ahs[s] + r * ASTR + a_q * 8),
                  hiA + (size_t)r * DD + kc + a_q * 8);
            cpa16((uint32_t)__cvta_generic_to_shared(Als[s] + r * ASTR + a_q * 8),
                  loA + (size_t)r * DD + kc + a_q * 8);
        }
        asm volatile("cp.async.commit_group;" ::: "memory");
    };
    auto loadBreg = [&](int kc) {
#pragma unroll
        for (int it = 0; it < WN; it++) {
            int g = tid + it * 256;
            int k = g / NQ4, nq = g % NQ4;
            breg[it] = *reinterpret_cast<const float4*>(B + (size_t)(kc + k) * Ntot + n0 + nq * 4);
        }
    };
    auto storeB = [&](int s) {
#pragma unroll
        for (int it = 0; it < WN; it++) {
            int g = tid + it * 256;
            int k = g / NQ4, nq = g % NQ4;
            float vals[4] = {breg[it].x, breg[it].y, breg[it].z, breg[it].w};
            __nv_bfloat16 h[4], l[4];
#pragma unroll
            for (int j = 0; j < 4; j++) split_bf16(vals[j], h[j], l[j]);
            __nv_bfloat162 h01 = __halves2bfloat162(h[0], h[1]);
            __nv_bfloat162 h23 = __halves2bfloat162(h[2], h[3]);
            __nv_bfloat162 l01 = __halves2bfloat162(l[0], l[1]);
            __nv_bfloat162 l23 = __halves2bfloat162(l[2], l[3]);
            uint2 uh, ul;
            uh.x = *reinterpret_cast<uint32_t*>(&h01); uh.y = *reinterpret_cast<uint32_t*>(&h23);
            ul.x = *reinterpret_cast<uint32_t*>(&l01); ul.y = *reinterpret_cast<uint32_t*>(&l23);
            *reinterpret_cast<uint2*>(&Bhs[s][k * NSTR + nq * 4]) = uh;
            *reinterpret_cast<uint2*>(&Bls[s][k * NSTR + nq * 4]) = ul;
        }
    };
    auto compute = [&](int s) {
        const __nv_bfloat16* Ah = Ahs[s];
        const __nv_bfloat16* Al = Als[s];
        const __nv_bfloat16* Bh = Bhs[s];
        const __nv_bfloat16* Bl = Bls[s];
#pragma unroll
        for (int ks = 0; ks < 2; ks++) {
            uint32_t ah[2][4], al[2][4], bh[4][2], bl[4][2];
#pragma unroll
            for (int mt = 0; mt < 2; mt++) {
                const __nv_bfloat16* pa = Ah + (wm * 32 + mt * 16 + fr) * ASTR + ks * 16 + fc;
                ldsm_x4(ah[mt], (uint32_t)__cvta_generic_to_shared(pa));
                const __nv_bfloat16* pl = Al + (wm * 32 + mt * 16 + fr) * ASTR + ks * 16 + fc;
                ldsm_x4(al[mt], (uint32_t)__cvta_generic_to_shared(pl));
            }
#pragma unroll
            for (int ntp = 0; ntp < 2; ntp++) {
                uint32_t r[4];
                const __nv_bfloat16* pb = Bh + (ks * 16 + fr) * NSTR + wn * 32 + ntp * 16 + fc;
                ldsm_x4t(r, (uint32_t)__cvta_generic_to_shared(pb));
                bh[2 * ntp][0] = r[0]; bh[2 * ntp][1] = r[1];
                bh[2 * ntp + 1][0] = r[2]; bh[2 * ntp + 1][1] = r[3];
                const __nv_bfloat16* pbl = Bl + (ks * 16 + fr) * NSTR + wn * 32 + ntp * 16 + fc;
                ldsm_x4t(r, (uint32_t)__cvta_generic_to_shared(pbl));
                bl[2 * ntp][0] = r[0]; bl[2 * ntp][1] = r[1];
                bl[2 * ntp + 1][0] = r[2]; bl[2 * ntp + 1][1] = r[3];
            }
#pragma unroll
            for (int mt = 0; mt < 2; mt++)
#pragma unroll
                for (int nt = 0; nt < 4; nt++) {
                    asm volatile(
                        "mma.sync.aligned.m16n8k16.row.col.f32.bf16.bf16.f32 "
                        "{%0,%1,%2,%3}, {%4,%5,%6,%7}, {%8,%9}, {%0,%1,%2,%3};"
                        : "+f"(acc[mt][nt][0]), "+f"(acc[mt][nt][1]),
                          "+f"(acc[mt][nt][2]), "+f"(acc[mt][nt][3])
                        : "r"(ah[mt][0]), "r"(ah[mt][1]), "r"(ah[mt][2]), "r"(ah[mt][3]),
                          "r"(bh[nt][0]), "r"(bh[nt][1]));
                    asm volatile(
                        "mma.sync.aligned.m16n8k16.row.col.f32.bf16.bf16.f32 "
                        "{%0,%1,%2,%3}, {%4,%5,%6,%7}, {%8,%9}, {%0,%1,%2,%3};"
                        : "+f"(acc[mt][nt][0]), "+f"(acc[mt][nt][1]),
                          "+f"(acc[mt][nt][2]), "+f"(acc[mt][nt][3])
                        : "r"(al[mt][0]), "r"(al[mt][1]), "r"(al[mt][2]), "r"(al[mt][3]),
                          "r"(bh[nt][0]), "r"(bh[nt][1]));
                    asm volatile(
                        "mma.sync.aligned.m16n8k16.row.col.f32.bf16.bf16.f32 "
                        "{%0,%1,%2,%3}, {%4,%5,%6,%7}, {%8,%9}, {%0,%1,%2,%3};"
                        : "+f"(acc[mt][nt][0]), "+f"(acc[mt][nt][1]),
                          "+f"(acc[mt][nt][2]), "+f"(acc[mt][nt][3])
                        : "r"(ah[mt][0]), "r"(ah[mt][1]), "r"(ah[mt][2]), "r"(ah[mt][3]),
                          "r"(bl[nt][0]), "r"(bl[nt][1]));
                }
        }
    };

    loadA(kb, 0);
    loadBreg(kb);
    storeB(0);
    asm volatile("cp.async.wait_group 0;" ::: "memory");
    __syncthreads();

    int cur = 0;
    for (int kc = kb; kc < kb + Kcta; kc += BK) {
        bool has = (kc + BK) < (kb + Kcta);
        if (has) {
            loadA(kc + BK, cur ^ 1);
            loadBreg(kc + BK);
        }
        compute(cur);
        if (has) {
            storeB(cur ^ 1);
            asm volatile("cp.async.wait_group 0;" ::: "memory");
            __syncthreads();
        }
        cur ^= 1;
    }

#pragma unroll
    for (int mt = 0; mt < 2; mt++) {
        int r0 = wm * 32 + mt * 16 + gid;
#pragma unroll
        for (int nt = 0; nt < 4; nt++) {
            int cc = n0 + wn * 32 + nt * 8 + qd * 2;
            if (r0 < M) {
                atomicAdd(&C[(size_t)r0 * Ntot + cc],     acc[mt][nt][0]);
                atomicAdd(&C[(size_t)r0 * Ntot + cc + 1], acc[mt][nt][1]);
            }
            if (r0 + 8 < M) {
                atomicAdd(&C[(size_t)(r0 + 8) * Ntot + cc],     acc[mt][nt][2]);
                atomicAdd(&C[(size_t)(r0 + 8) * Ntot + cc + 1], acc[mt][nt][3]);
            }
        }
    }
}

#define GEMM_SMEM_12 ((4 * (128 * ASTR) + 4 * (BK * 72)) * 2)
#define GEMM_SMEM_3  ((4 * (64 * ASTR) + 4 * (BK * 136)) * 2)

// ---------------------------------------------------------------------------
// LayerNorm per row (adds deferred bias badd) -> hi/lo bf16.
// ALSO zeroes the h accumulator row (fold of the old k_zero launch).
// ---------------------------------------------------------------------------
__global__ void k_ln(const float* __restrict__ X, const float* __restrict__ badd,
                     __nv_bfloat16* __restrict__ hiA, __nv_bfloat16* __restrict__ loA,
                     const float* __restrict__ gam, const float* __restrict__ bet,
                     float* __restrict__ h_out) {
    int m = blockIdx.x;
    if (m == NM1) {
        for (int d = threadIdx.x; d < DD; d += 256) {
            hiA[(size_t)m * DD + d] = __float2bfloat16(0.f);
            loA[(size_t)m * DD + d] = __float2bfloat16(0.f);
        }
        return;
    }
    // fold: zero h row m (GEMM2 accumulates into it next)
    for (int d = threadIdx.x; d < DD; d += 256) h_out[(size_t)m * DD + d] = 0.f;

    const float* x = X + (size_t)m * DD;
    __shared__ float red[32];
    __shared__ float s_mu, s_rstd;

    float s = 0.f;
    for (int d = threadIdx.x; d < DD; d += 256) s += x[d] + badd[d];
    for (int o = 16; o; o >>= 1) s += __shfl_down_sync(0xffffffffu, s, o);
    int w = threadIdx.x >> 5, lane = threadIdx.x & 31;
    if (lane == 0) red[w] = s;
    __syncthreads();
    if (threadIdx.x == 0) {
        float t = 0.f;
        for (int i = 0; i < 8; i++) t += red[i];
        s_mu = t / (float)DD;
    }
    __syncthreads();
    float mu = s_mu;

    float s2 = 0.f;
    for (int d = threadIdx.x; d < DD; d += 256) {
        float v = x[d] + badd[d] - mu; s2 += v * v;
    }
    for (int o = 16; o; o >>= 1) s2 += __shfl_down_sync(0xffffffffu, s2, o);
    if (lane == 0) red[w] = s2;
    __syncthreads();
    if (threadIdx.x == 0) {
        float t = 0.f;
        for (int i = 0; i < 8; i++) t += red[i];
        s_rstd = rsqrtf(t / (float)DD + 1e-5f);
    }
    __syncthreads();
    float rstd = s_rstd;

    for (int d = threadIdx.x; d < DD; d += 256) {
        float yv = (x[d] + badd[d] - mu) * rstd * gam[d] + bet[d];
        __nv_bfloat16 h, l;
        split_bf16(yv, h, l);
        hiA[(size_t)m * DD + d] = h;
        loA[(size_t)m * DD + d] = l;
    }
}

// ---------------------------------------------------------------------------
// Gate head: deferred bias b1, exact GELU, W2 matvec, Gumbel softmax y
// ---------------------------------------------------------------------------
__global__ void k_gate(const float* __restrict__ H, const float* __restrict__ b1,
                       const float* __restrict__ W2,
                       const float* __restrict__ b2, const float* __restrict__ gu,
                       float* __restrict__ out_gate, float* __restrict__ y) {
    int m = blockIdx.x;
    const float* h = H + (size_t)m * DD;
    float a0 = 0.f, a1 = 0.f;
    for (int k = threadIdx.x; k < DD; k += 128) {
        float hr = h[k] + b1[k];
        float hv = 0.5f * hr * (1.f + erff(hr * 0.70710678118654752440f));
        a0 += hv * W2[2 * k + 0];
        a1 += hv * W2[2 * k + 1];
    }
    for (int o = 16; o; o >>= 1) {
        a0 += __shfl_down_sync(0xffffffffu, a0, o);
        a1 += __shfl_down_sync(0xffffffffu, a1, o);
    }
    __shared__ float r0[4], r1[4];
    int w = threadIdx.x >> 5, lane = threadIdx.x & 31;
    if (lane == 0) { r0[w] = a0; r1[w] = a1; }
    __syncthreads();
    if (threadIdx.x == 0) {
        float l0 = r0[0] + r0[1] + r0[2] + r0[3] + b2[0];
        float l1 = r1[0] + r1[1] + r1[2] + r1[3] + b2[1];
        out_gate[2 * m + 0] = l0;
        out_gate[2 * m + 1] = l1;
        float u0 = gu[2 * m + 0], u1 = gu[2 * m + 1];
        float g0 = -logf(-logf(u0 + 1e-20f) + 1e-20f);
        float g1 = -logf(-logf(u1 + 1e-20f) + 1e-20f);
        float s0 = (l0 + 0.1f * g0) * 2.0f;
        float s1 = (l1 + 0.1f * g1) * 2.0f;
        y[m] = 1.0f / (1.0f + expf(s0 - s1));
    }
}

// ---------------------------------------------------------------------------
// Parallel top-8 of 127 + z_hard + selection list
// ---------------------------------------------------------------------------
__global__ void k_topk(const float* __restrict__ y, float* __restrict__ out_z) {
    __shared__ float sv[128];
    __shared__ int   si[128];
    int tid = threadIdx.x;
    float val = (tid < NM1) ? y[tid] : -1e30f;
    if (tid == 0) { out_z[0] = 1.f; g_sel[0] = 0; }
    if (tid < NM1) out_z[tid + 1] = 0.f;
    __syncthreads();
    for (int r = 0; r < NC; r++) {
        sv[tid] = val; si[tid] = tid;
        __syncthreads();
        for (int o = 64; o; o >>= 1) {
            if (tid < o) {
                float ov = sv[tid + o]; int oi = si[tid + o];
                if (ov > sv[tid] || (ov == sv[tid] && oi < si[tid])) {
                    sv[tid] = ov; si[tid] = oi;
                }
            }
            __syncthreads();
        }
        int wn = si[0];
        if (tid == wn) val = -1e30f;
        if (tid == 0) { g_sel[r + 1] = wn + 1; out_z[wn + 1] = 1.f; }
        __syncthreads();
    }
}

// ---------------------------------------------------------------------------
// Pooled thumbnail features -> hi/lo bf16 rows 0..63.
// ALSO initializes out_thumb = bias (fold of the old bias-init launches).
// ---------------------------------------------------------------------------
__global__ void k_pool(const float* __restrict__ v,
                       __nv_bfloat16* __restrict__ hiA, __nv_bfloat16* __restrict__ loA,
                       float* __restrict__ out_thumb, const float* __restrict__ b_th) {
    int b = blockIdx.x;
    // fold: out_thumb[q*LMq + n] = b_th[n], grid-stride over 262144 elements
    {
        int stride = gridDim.x * blockDim.x;              // 192*128 = 24576
        for (int idx = b * blockDim.x + threadIdx.x; idx < NQk * LMq; idx += stride)
            out_thumb[idx] = b_th[idx & (LMq - 1)];
    }

    int q = b / 3, c = b % 3;
    int d = c * 512 + threadIdx.x * 4;
    float ax = 0.f, ay = 0.f, az = 0.f, aw = 0.f;
    for (int s = 0; s <= NC; s++) {
        int f = g_sel[s];
        const float* base = v + ((size_t)f * PP + q * 9) * DD + d;
#pragma unroll
        for (int p = 0; p < 9; p++) {
            float4 x = *reinterpret_cast<const float4*>(base + (size_t)p * DD);
            ax += x.x; ay += x.y; az += x.z; aw += x.w;
        }
    }
    const float inv = 1.0f / 81.0f;
    float vals[4] = {ax * inv, ay * inv, az * inv, aw * inv};
#pragma unroll
    for (int j = 0; j < 4; j++) {
        __nv_bfloat16 h, l;
        split_bf16(vals[j], h, l);
        hiA[(size_t)q * DD + d + j] = h;
        loA[(size_t)q * DD + d + j] = l;
    }
}

// ---------------------------------------------------------------------------
// Launch (9 launches total; all fills folded into producers)
// ---------------------------------------------------------------------------
extern "C" void kernel_launch(void* const* d_in, const int* in_sizes, int n_in,
                              void* d_out, int out_size) {
    const float* v     = (const float*)d_in[0];
    const float* gu    = (const float*)d_in[1];
    const float* W_agg = (const float*)d_in[2];
    const float* b_agg = (const float*)d_in[3];
    const float* ln_g  = (const float*)d_in[4];
    const float* ln_b  = (const float*)d_in[5];
    const float* W1    = (const float*)d_in[6];
    const float* b1    = (const float*)d_in[7];
    const float* W2    = (const float*)d_in[8];
    const float* b2    = (const float*)d_in[9];
    const float* W_th  = (const float*)d_in[10];
    const float* b_th  = (const float*)d_in[11];

    float* out       = (float*)d_out;
    float* out_gate  = out;
    float* out_thumb = out + NM1 * 2;
    float* out_z     = out_thumb + NQk * LMq;

    float* scr = nullptr;
    cudaGetSymbolAddress((void**)&scr, g_scratch);
    float* mp2  = scr + OFF_MP;
    float* feat = scr + OFF_FEAT;
    float* h    = scr + OFF_H;
    float* yv   = scr + OFF_Y;

    __nv_bfloat16 *hiA, *loA;
    cudaGetSymbolAddress((void**)&hiA, g_hiA);
    cudaGetSymbolAddress((void**)&loA, g_loA);

    cudaFuncSetAttribute(k_gemm_fused<4, 2>, cudaFuncAttributeMaxDynamicSharedMemorySize, GEMM_SMEM_12);
    cudaFuncSetAttribute(k_gemm_fused<2, 4>, cudaFuncAttributeMaxDynamicSharedMemorySize, GEMM_SMEM_3);

    // 1: patch sums + feat zero-fill
    k_mp<<<NF * SPLIT, 384>>>(v, mp2, feat);
    // 2: EMA -> hi/lo A
    k_ema<<<(DD / 256) * 8, 256>>>(mp2, hiA, loA);

    // 3: GEMM1  feat += ema @ W_agg   (b_agg folded into k_ln)
    {
        dim3 grid(DD / 64, 1, 12);
        k_gemm_fused<4, 2><<<grid, 256, GEMM_SMEM_12>>>(hiA, loA, W_agg, feat, NM1, DD, DD / 12);
    }

    // 4: LayerNorm (adds b_agg, emits hi/lo A) + h zero-fill
    k_ln<<<NM1 + 1, 256>>>(feat, b_agg, hiA, loA, ln_g, ln_b, h);

    // 5: GEMM2  h += xn @ W1   (b1 folded into k_gate)
    {
        dim3 grid(DD / 64, 1, 12);
        k_gemm_fused<4, 2><<<grid, 256, GEMM_SMEM_12>>>(hiA, loA, W1, h, NM1, DD, DD / 12);
    }

    // 6-8: gate, topk, pool (+ out_thumb bias fill)
    k_gate<<<NM1, 128>>>(h, b1, W2, b2, gu, out_gate, yv);
    k_topk<<<1, 128>>>(yv, out_z);
    k_pool<<<NQk * 3, 128>>>(v, hiA, loA, out_thumb, b_th);

    // 9: GEMM3  thumbnail += pooled @ W_th   (M=64 tile, N=128 tile, split 8)
    {
        dim3 grid(LMq / 128, 1, 8);
        k_gemm_fused<2, 4><<<grid, 256, GEMM_SMEM_3>>>(hiA, loA, W_th, out_thumb, NQk, LMq, DD / 8);
    }
}